// round 12
// baseline (speedup 1.0000x reference)
#include <cuda_runtime.h>
#include <cuda_bf16.h>
#include <cuda_fp16.h>
#include <cstdint>
#include <math.h>

#define B_ 1024
#define N_ 6
#define D_ 1280
#define STEPS_ 5
#define TOT (B_*N_*D_)
#define DDLL (1280LL*1280LL)

// ---------------- scratch (static device globals; no allocations) -------------
__device__ float g_gx [TOT];
__device__ float g_prer[TOT];
__device__ float g_prez[TOT];
__device__ float g_pret[TOT];
__device__ float g_pretD[TOT];
__device__ __half g_gxf [TOT];
__device__ __half g_ainf[TOT];
__device__ __half g_aoutf[TOT];
__device__ __half g_rgxf[TOT];
// 21 transposed weight matrices (1280x1280), fp16 hi/lo (22-bit effective)
__device__ __half g_wth[21u*1280u*1280u];
__device__ __half g_wtl[21u*1280u*1280u];

// ---------------- PTX helpers (stable ISA only) --------------------------------
__device__ __forceinline__ uint32_t smem_u32(const void* p) {
    uint32_t a;
    asm("{ .reg .u64 t; cvta.to.shared.u64 t, %1; cvt.u32.u64 %0, t; }" : "=r"(a) : "l"(p));
    return a;
}
__device__ __forceinline__ void cpa16(uint32_t dst, const void* src) {
    asm volatile("cp.async.cg.shared.global [%0], [%1], 16;" :: "r"(dst), "l"(src));
}
#define CPA_COMMIT() asm volatile("cp.async.commit_group;" ::: "memory")
#define CPA_WAIT1()  asm volatile("cp.async.wait_group 1;" ::: "memory")
#define CPA_WAIT0()  asm volatile("cp.async.wait_group 0;" ::: "memory")

#define LDSM4(r, a) \
    asm volatile("ldmatrix.sync.aligned.m8n8.x4.shared.b16 {%0,%1,%2,%3}, [%4];" \
        : "=r"((r)[0]), "=r"((r)[1]), "=r"((r)[2]), "=r"((r)[3]) : "r"(a))

__device__ __forceinline__ void mma16816(float* c, const uint32_t* a, const uint32_t* b) {
    asm volatile("mma.sync.aligned.m16n8k16.row.col.f32.f16.f16.f32 "
        "{%0,%1,%2,%3}, {%4,%5,%6,%7}, {%8,%9}, {%0,%1,%2,%3};"
        : "+f"(c[0]), "+f"(c[1]), "+f"(c[2]), "+f"(c[3])
        : "r"(a[0]), "r"(a[1]), "r"(a[2]), "r"(a[3]), "r"(b[0]), "r"(b[1]));
}

__device__ __forceinline__ void split2h(float v, __half& h, __half& l) {
    h = __float2half(v);
    l = __float2half(v - __half2float(h));
}

// ---------------- fp16 2-pass batched GEMM (mma.sync path) ----------------------
// CTA tile 128 rows x 128 cols, 256 threads, 8 warps (2x4 grid, warp tile 64x32),
// 2 CTAs/SM. A: single fp16. W: fp16 hi/lo (exact). 2 MMA passes: A*Wh + A*Wl.
// Inner loop: A fragments persistent, B fragments transient (low reg pressure).
// mode 0: fp16 out (+bias); 1: fp32 out (+bias)
struct GSeg {
    const __half* A;
    const __half* Bh; const __half* Bl;   // W transposed [n][k]
    const float* bias; long long lda;
};
struct GJob {
    GSeg seg[3];
    float* C; __half* Ch;
    long long ldc; int nseg; int mode;
};
struct GBatch { GJob job[6]; };

// per stage: A 16K | Bh 16K | Bl 16K = 48K; 2 stages = 96K
#define ST_BYTES 49152
#define SMEM_TOTAL (2*ST_BYTES)

__global__ void __launch_bounds__(256, 2) mma_gemm(GBatch batch) {
    extern __shared__ char smem[];
    const GJob& job = batch.job[blockIdx.z];
    const uint32_t sb = smem_u32(smem);
    const int tid = threadIdx.x;
    const int lane = tid & 31, wid = tid >> 5;
    const int wm = wid & 1, wn = wid >> 1;          // 2x4 warp grid, warp tile 64x32
    const int row0 = blockIdx.y * 128;
    const int col0 = blockIdx.x * 128;

    float acc[4][4][4];
#pragma unroll
    for (int mt = 0; mt < 4; mt++)
#pragma unroll
        for (int nt = 0; nt < 4; nt++)
#pragma unroll
            for (int q = 0; q < 4; q++) acc[mt][nt][q] = 0.f;

    const int nchunks = job.nseg * 20;

    auto load_chunk = [&](int c, int s) {
        const int sg = c / 20, kc = c % 20;
        const GSeg& S = job.seg[sg];
        const uint32_t base = sb + s * ST_BYTES;
        const __half* gA  = S.A  + (long long)row0 * S.lda + kc * 64;
        const __half* gBh = S.Bh + (long long)col0 * 1280 + kc * 64;
        const __half* gBl = S.Bl + (long long)col0 * 1280 + kc * 64;
        // A: 128 rows x 128B
#pragma unroll
        for (int i = 0; i < 4; i++) {
            int idx = tid + i * 256;
            int r = idx >> 3, c8 = idx & 7;
            uint32_t sw = (uint32_t)(r * 128 + ((c8 ^ (r & 7)) << 4));
            cpa16(base + sw, gA + (long long)r * S.lda + c8 * 8);
        }
        // B: 128 rows x 128B (hi + lo)
#pragma unroll
        for (int i = 0; i < 4; i++) {
            int idx = tid + i * 256;
            int r = idx >> 3, c8 = idx & 7;
            uint32_t sw = (uint32_t)(r * 128 + ((c8 ^ (r & 7)) << 4));
            long long gb = (long long)r * 1280 + c8 * 8;
            cpa16(base + 16384 + sw, gBh + gb);
            cpa16(base + 32768 + sw, gBl + gb);
        }
        CPA_COMMIT();
    };

    load_chunk(0, 0);

    const int g = lane >> 3;
    for (int c = 0; c < nchunks; c++) {
        const int s = c & 1;
        if (c + 1 < nchunks) { load_chunk(c + 1, s ^ 1); CPA_WAIT1(); }
        else                 { CPA_WAIT0(); }
        __syncthreads();

        const uint32_t AB  = sb + s * ST_BYTES;
        const uint32_t BhB = AB + 16384;
        const uint32_t BlB = AB + 32768;

#pragma unroll
        for (int ks = 0; ks < 4; ks++) {
            // A fragments persistent (all 4 mt)
            uint32_t a[4][4];
#pragma unroll
            for (int mt = 0; mt < 4; mt++) {
                int ar = wm * 64 + mt * 16 + ((g & 1) << 3) + (lane & 7);
                int ac = ks * 2 + (g >> 1);
                uint32_t off = (uint32_t)(ar * 128 + ((ac ^ (ar & 7)) << 4));
                LDSM4(a[mt], AB + off);
            }
            // B fragments transient per nt-pair
#pragma unroll
            for (int p = 0; p < 2; p++) {
                int br = wn * 32 + p * 16 + ((g >> 1) << 3) + (lane & 7);
                int bc = ks * 2 + (g & 1);
                uint32_t off = (uint32_t)(br * 128 + ((bc ^ (br & 7)) << 4));
                uint32_t t[4];
                LDSM4(t, BhB + off);
#pragma unroll
                for (int mt = 0; mt < 4; mt++) {
                    mma16816(acc[mt][2*p],     a[mt], t);
                    mma16816(acc[mt][2*p + 1], a[mt], t + 2);
                }
                LDSM4(t, BlB + off);
#pragma unroll
                for (int mt = 0; mt < 4; mt++) {
                    mma16816(acc[mt][2*p],     a[mt], t);
                    mma16816(acc[mt][2*p + 1], a[mt], t + 2);
                }
            }
        }
        __syncthreads();
    }

    // ---- epilogue: registers -> global directly ----
    const long long ldc = job.ldc;
    const int rbase = row0 + wm * 64;
    const int cbase = col0 + wn * 32;
#pragma unroll
    for (int nt = 0; nt < 4; nt++) {
        const int col = cbase + nt * 8 + ((lane & 3) << 1);
        float bv0 = 0.f, bv1 = 0.f;
        for (int sg = 0; sg < job.nseg; sg++) {
            const float* bp = job.seg[sg].bias;
            if (bp) { bv0 += bp[col]; bv1 += bp[col + 1]; }
        }
#pragma unroll
        for (int mt = 0; mt < 4; mt++) {
            const int r1 = rbase + mt * 16 + (lane >> 2);
            const int r2 = r1 + 8;
            const float* a4 = acc[mt][nt];
            if (job.mode == 1) {
                *(float2*)&job.C[(long long)r1 * ldc + col] = make_float2(a4[0] + bv0, a4[1] + bv1);
                *(float2*)&job.C[(long long)r2 * ldc + col] = make_float2(a4[2] + bv0, a4[3] + bv1);
            } else {
                *(__half2*)&job.Ch[(long long)r1 * ldc + col] =
                    __halves2half2(__float2half(a4[0] + bv0), __float2half(a4[1] + bv1));
                *(__half2*)&job.Ch[(long long)r2 * ldc + col] =
                    __halves2half2(__float2half(a4[2] + bv0), __float2half(a4[3] + bv1));
            }
        }
    }
}

// ---------------- weight transpose + fp16 split (once per call) -----------------
__global__ void wconv_k(const float* __restrict__ Win, const float* __restrict__ Wout,
                        const float* __restrict__ Wr, const float* __restrict__ Wz,
                        const float* __restrict__ Wt,
                        __half* __restrict__ wth, __half* __restrict__ wtl) {
    __shared__ float tile[32][33];
    const int slot = blockIdx.z;
    const int f0 = blockIdx.x * 32, d0 = blockIdx.y * 32;
    const float* base;
    if (slot < 6)       base = Win  + (long long)slot * DDLL;
    else if (slot < 12) base = Wout + (long long)(slot - 6) * DDLL;
    else {
        int gq = (slot - 12) / 3, q = (slot - 12) % 3;
        base = (gq == 0 ? Wr : (gq == 1 ? Wz : Wt)) + (long long)q * DDLL;
    }
    for (int i = threadIdx.y; i < 32; i += 8)
        tile[i][threadIdx.x] = base[(long long)(d0 + i) * 1280 + f0 + threadIdx.x];
    __syncthreads();
    __half* oh = wth + (long long)slot * DDLL;
    __half* ol = wtl + (long long)slot * DDLL;
    for (int i = threadIdx.y; i < 32; i += 8) {
        float v = tile[threadIdx.x][i];
        __half h, l; split2h(v, h, l);
        oh[(long long)(f0 + i) * 1280 + d0 + threadIdx.x] = h;
        ol[(long long)(f0 + i) * 1280 + d0 + threadIdx.x] = l;
    }
}

// ---------------- elementwise kernels ------------------------------------------
__global__ void copy_x_k(const float* __restrict__ x, float* __restrict__ gx,
                         __half* __restrict__ gf) {
    for (int i = blockIdx.x * blockDim.x + threadIdx.x; i < TOT; i += gridDim.x * blockDim.x) {
        float v = x[i]; gx[i] = v;
        gf[i] = __float2half(v);
    }
}

__global__ void zero_slices_k(__half* af, __half* of) {
    const int na[3] = {0, 4, 5};
    const int no[3] = {3, 4, 5};
    int total = 6 * B_ * D_;
    for (int idx = blockIdx.x * blockDim.x + threadIdx.x; idx < total;
         idx += gridDim.x * blockDim.x) {
        int s = idx / (B_ * D_);
        int r = idx % (B_ * D_);
        int b = r / D_, d = r % D_;
        __half z = __float2half(0.f);
        if (s < 3) af[((long long)b * N_ + na[s]) * D_ + d] = z;
        else       of[((long long)b * N_ + no[s - 3]) * D_ + d] = z;
    }
}

__global__ void sig_rgx_k(const float* __restrict__ prer, const float* __restrict__ gx,
                          __half* __restrict__ rf) {
    for (int i = blockIdx.x * blockDim.x + threadIdx.x; i < TOT; i += gridDim.x * blockDim.x) {
        float r = 1.f / (1.f + expf(-prer[i]));
        rf[i] = __float2half(r * gx[i]);
    }
}

__global__ void update_k(const float* __restrict__ prez, const float* __restrict__ pret,
                         const float* __restrict__ pretD, float* __restrict__ gx,
                         __half* __restrict__ gf) {
    for (int i = blockIdx.x * blockDim.x + threadIdx.x; i < TOT; i += gridDim.x * blockDim.x) {
        float z = 1.f / (1.f + expf(-prez[i]));
        float h = tanhf(pret[i] + pretD[i]);
        float gv = gx[i];
        float ng = gv + z * (h - gv);
        gx[i] = ng;
        gf[i] = __float2half(ng);
    }
}

__global__ void transpose_k(const float* __restrict__ gx, float* __restrict__ out) {
    for (int idx = blockIdx.x * blockDim.x + threadIdx.x; idx < TOT;
         idx += gridDim.x * blockDim.x) {
        int b = idx / (N_ * D_);
        int r = idx % (N_ * D_);
        int d = r / N_, n = r % N_;
        out[idx] = gx[((long long)b * N_ + n) * D_ + d];
    }
}

// ---------------- host orchestration ------------------------------------------
extern "C" void kernel_launch(void* const* d_in, const int* in_sizes, int n_in,
                              void* d_out, int out_size) {
    const float* x     = (const float*)d_in[0];
    const float* W_in  = (const float*)d_in[2];
    const float* b_in  = (const float*)d_in[3];
    const float* W_out = (const float*)d_in[4];
    const float* b_out = (const float*)d_in[5];
    const float* W_r   = (const float*)d_in[6];
    const float* b_r   = (const float*)d_in[7];
    const float* W_z   = (const float*)d_in[8];
    const float* b_z   = (const float*)d_in[9];
    const float* W_t   = (const float*)d_in[10];
    const float* b_t   = (const float*)d_in[11];
    float* out = (float*)d_out;

    float *gx, *prer, *prez, *pret, *pretD;
    __half *gxf, *ainf, *aoutf, *rgxf, *wth, *wtl;
    cudaGetSymbolAddress((void**)&gx,    g_gx);
    cudaGetSymbolAddress((void**)&prer,  g_prer);
    cudaGetSymbolAddress((void**)&prez,  g_prez);
    cudaGetSymbolAddress((void**)&pret,  g_pret);
    cudaGetSymbolAddress((void**)&pretD, g_pretD);
    cudaGetSymbolAddress((void**)&gxf,   g_gxf);
    cudaGetSymbolAddress((void**)&ainf,  g_ainf);
    cudaGetSymbolAddress((void**)&aoutf, g_aoutf);
    cudaGetSymbolAddress((void**)&rgxf,  g_rgxf);
    cudaGetSymbolAddress((void**)&wth,   g_wth);
    cudaGetSymbolAddress((void**)&wtl,   g_wtl);

    cudaFuncSetAttribute(mma_gemm, cudaFuncAttributeMaxDynamicSharedMemorySize, SMEM_TOTAL);

    // side stream + events (created once; host-side resources only)
    static cudaStream_t s1 = nullptr;
    static cudaEvent_t evFork = nullptr, evJoin = nullptr;
    if (!s1) {
        cudaStreamCreateWithFlags(&s1, cudaStreamNonBlocking);
        cudaEventCreateWithFlags(&evFork, cudaEventDisableTiming);
        cudaEventCreateWithFlags(&evJoin, cudaEventDisableTiming);
    }

    const long long ldn = (long long)N_ * D_;
    auto wslot = [&](int s) { return (long long)s * DDLL; };

    // ---- Phase A (mode 0): edge propagation ----
    GBatch bA = {};
    {
        auto seg_in = [&](int src, int et) {
            GSeg s{};
            s.A = gxf + (long long)src * D_; s.lda = ldn;
            s.Bh = wth + wslot(et); s.Bl = wtl + wslot(et);
            s.bias = b_in + (long long)et * D_;
            return s;
        };
        auto seg_out = [&](int tgt, int et) {
            GSeg s{};
            s.A = gxf + (long long)tgt * D_; s.lda = ldn;
            s.Bh = wth + wslot(6 + et); s.Bl = wtl + wslot(6 + et);
            s.bias = b_out + (long long)et * D_;
            return s;
        };
        auto setC = [&](GJob& j, __half* cf, int node) {
            j.Ch = cf + (long long)node * D_;
            j.ldc = ldn; j.mode = 0;
        };
        bA.job[0].seg[0] = seg_in(0, 2); bA.job[0].seg[1] = seg_in(1, 4); bA.job[0].seg[2] = seg_in(2, 5);
        bA.job[0].nseg = 3; setC(bA.job[0], ainf, 3);
        bA.job[1].seg[0] = seg_out(1, 0); bA.job[1].seg[1] = seg_out(2, 1); bA.job[1].seg[2] = seg_out(3, 2);
        bA.job[1].nseg = 3; setC(bA.job[1], aoutf, 0);
        bA.job[2].seg[0] = seg_in(0, 1); bA.job[2].seg[1] = seg_in(1, 3);
        bA.job[2].nseg = 2; setC(bA.job[2], ainf, 2);
        bA.job[3].seg[0] = seg_out(2, 3); bA.job[3].seg[1] = seg_out(3, 4);
        bA.job[3].nseg = 2; setC(bA.job[3], aoutf, 1);
        bA.job[4].seg[0] = seg_in(0, 0); bA.job[4].nseg = 1; setC(bA.job[4], ainf, 1);
        bA.job[5].seg[0] = seg_out(3, 5); bA.job[5].nseg = 1; setC(bA.job[5], aoutf, 2);
    }

    auto mkseg = [&](const __half* A, int gslot, const float* bias) {
        GSeg s{};
        s.A = A; s.lda = D_;
        s.Bh = wth + wslot(gslot); s.Bl = wtl + wslot(gslot);
        s.bias = bias;
        return s;
    };

    // ---- Phase B0 (mode 1): prer only ----
    GBatch bB0 = {};
    bB0.job[0].seg[0] = mkseg(ainf, 12, b_r);
    bB0.job[0].seg[1] = mkseg(aoutf, 13, 0);
    bB0.job[0].seg[2] = mkseg(gxf, 14, 0);
    bB0.job[0].nseg = 3; bB0.job[0].C = prer; bB0.job[0].ldc = D_; bB0.job[0].mode = 1;

    // ---- Phase B12 (mode 1): prez, pret-partial ----
    GBatch bB12 = {};
    bB12.job[0].seg[0] = mkseg(ainf, 15, b_z);
    bB12.job[0].seg[1] = mkseg(aoutf, 16, 0);
    bB12.job[0].seg[2] = mkseg(gxf, 17, 0);
    bB12.job[0].nseg = 3; bB12.job[0].C = prez; bB12.job[0].ldc = D_; bB12.job[0].mode = 1;
    bB12.job[1].seg[0] = mkseg(ainf, 18, b_t);
    bB12.job[1].seg[1] = mkseg(aoutf, 19, 0);
    bB12.job[1].nseg = 2; bB12.job[1].C = pret; bB12.job[1].ldc = D_; bB12.job[1].mode = 1;

    // ---- Phase D (mode 1): pretD = (r*gx) @ Wt2 ----
    GBatch bD = {};
    {
        GSeg s{};
        s.A = rgxf; s.lda = D_;
        s.Bh = wth + wslot(20); s.Bl = wtl + wslot(20); s.bias = 0;
        bD.job[0].seg[0] = s; bD.job[0].nseg = 1;
        bD.job[0].C = pretD; bD.job[0].ldc = D_; bD.job[0].mode = 1;
    }

    // ---- run ----
    wconv_k<<<dim3(40, 40, 21), dim3(32, 8)>>>(W_in, W_out, W_r, W_z, W_t, wth, wtl);
    copy_x_k<<<2048, 256>>>(x, gx, gxf);
    zero_slices_k<<<2048, 256>>>(ainf, aoutf);

    for (int step = 0; step < STEPS_; step++) {
        mma_gemm<<<dim3(10, 8, 6),  256, SMEM_TOTAL>>>(bA);    // edges -> a_in/a_out (fp16)
        mma_gemm<<<dim3(10, 48, 1), 256, SMEM_TOTAL>>>(bB0);   // prer
        cudaEventRecord(evFork, 0);
        cudaStreamWaitEvent(s1, evFork, 0);
        sig_rgx_k<<<2048, 256, 0, s1>>>(prer, gx, rgxf);                 // side stream
        mma_gemm<<<dim3(10, 48, 1), 256, SMEM_TOTAL, s1>>>(bD);          // pretD
        cudaEventRecord(evJoin, s1);
        mma_gemm<<<dim3(10, 48, 2), 256, SMEM_TOTAL>>>(bB12);  // prez, pret (overlaps side)
        cudaStreamWaitEvent(0, evJoin, 0);
        update_k<<<2048, 256>>>(prez, pret, pretD, gx, gxf);
    }
    transpose_k<<<2048, 256>>>(gx, out);
}

// round 13
// speedup vs baseline: 1.0326x; 1.0326x over previous
#include <cuda_runtime.h>
#include <cuda_bf16.h>
#include <cuda_fp16.h>
#include <cstdint>
#include <math.h>

#define B_ 1024
#define N_ 6
#define D_ 1280
#define STEPS_ 5
#define TOT (B_*N_*D_)
#define DDLL (1280LL*1280LL)

// ---------------- scratch (static device globals; no allocations) -------------
__device__ float g_gx [TOT];
__device__ float g_prer[TOT];
__device__ float g_prez[TOT];
__device__ float g_pret[TOT];
__device__ float g_pretD[TOT];
__device__ __half g_gxf [TOT];
__device__ __half g_ainf[TOT];
__device__ __half g_aoutf[TOT];
__device__ __half g_rgxf[TOT];
// 21 transposed weight matrices (1280x1280), fp16 hi/lo (22-bit effective)
__device__ __half g_wth[21u*1280u*1280u];
__device__ __half g_wtl[21u*1280u*1280u];

// ---------------- PTX helpers (stable ISA only) --------------------------------
__device__ __forceinline__ uint32_t smem_u32(const void* p) {
    uint32_t a;
    asm("{ .reg .u64 t; cvta.to.shared.u64 t, %1; cvt.u32.u64 %0, t; }" : "=r"(a) : "l"(p));
    return a;
}
__device__ __forceinline__ void cpa16(uint32_t dst, const void* src) {
    asm volatile("cp.async.cg.shared.global [%0], [%1], 16;" :: "r"(dst), "l"(src));
}
#define CPA_COMMIT() asm volatile("cp.async.commit_group;" ::: "memory")
#define CPA_WAIT1()  asm volatile("cp.async.wait_group 1;" ::: "memory")
#define CPA_WAIT0()  asm volatile("cp.async.wait_group 0;" ::: "memory")

#define LDSM4(r, a) \
    asm volatile("ldmatrix.sync.aligned.m8n8.x4.shared.b16 {%0,%1,%2,%3}, [%4];" \
        : "=r"((r)[0]), "=r"((r)[1]), "=r"((r)[2]), "=r"((r)[3]) : "r"(a))

__device__ __forceinline__ void mma16816(float* c, const uint32_t* a, const uint32_t* b) {
    asm volatile("mma.sync.aligned.m16n8k16.row.col.f32.f16.f16.f32 "
        "{%0,%1,%2,%3}, {%4,%5,%6,%7}, {%8,%9}, {%0,%1,%2,%3};"
        : "+f"(c[0]), "+f"(c[1]), "+f"(c[2]), "+f"(c[3])
        : "r"(a[0]), "r"(a[1]), "r"(a[2]), "r"(a[3]), "r"(b[0]), "r"(b[1]));
}

__device__ __forceinline__ void split2h(float v, __half& h, __half& l) {
    h = __float2half(v);
    l = __float2half(v - __half2float(h));
}

// ---------------- shared job structs --------------------------------------------
struct GSeg {
    const __half* A;
    const __half* Bh; const __half* Bl;   // W transposed [n][k]
    const float* bias; long long lda;
};
struct GJob {
    GSeg seg[3];
    float* C; __half* Ch;
    long long ldc; int nseg; int mode;    // 0: fp16 out (+bias); 1: fp32 out (+bias)
};
struct GBatch { GJob job[6]; };

// ================= kernel 1: 128x64 tiles (phase A — small M, uneven jobs) ======
// 256 threads, 8 warps (4x2 grid, warp tile 32x32), 2 CTAs/SM. (R10-proven: 99 regs)
#define STA_BYTES 32768
#define SMEM_A_TOTAL (2*STA_BYTES)

__global__ void __launch_bounds__(256, 2) mma_gemmA(GBatch batch) {
    extern __shared__ char smem[];
    const GJob& job = batch.job[blockIdx.z];
    const uint32_t sb = smem_u32(smem);
    const int tid = threadIdx.x;
    const int lane = tid & 31, wid = tid >> 5;
    const int wm = wid & 3, wn = wid >> 2;          // 4x2 warp grid, warp tile 32x32
    const int row0 = blockIdx.y * 128;
    const int col0 = blockIdx.x * 64;

    float acc[2][4][4];
#pragma unroll
    for (int mt = 0; mt < 2; mt++)
#pragma unroll
        for (int nt = 0; nt < 4; nt++)
#pragma unroll
            for (int q = 0; q < 4; q++) acc[mt][nt][q] = 0.f;

    const int nchunks = job.nseg * 20;

    auto load_chunk = [&](int c, int s) {
        const int sg = c / 20, kc = c % 20;
        const GSeg& S = job.seg[sg];
        const uint32_t base = sb + s * STA_BYTES;
        const __half* gA  = S.A  + (long long)row0 * S.lda + kc * 64;
        const __half* gBh = S.Bh + (long long)col0 * 1280 + kc * 64;
        const __half* gBl = S.Bl + (long long)col0 * 1280 + kc * 64;
#pragma unroll
        for (int i = 0; i < 4; i++) {
            int idx = tid + i * 256;
            int r = idx >> 3, c8 = idx & 7;
            uint32_t sw = (uint32_t)(r * 128 + ((c8 ^ (r & 7)) << 4));
            cpa16(base + sw, gA + (long long)r * S.lda + c8 * 8);
        }
#pragma unroll
        for (int i = 0; i < 2; i++) {
            int idx = tid + i * 256;
            int r = idx >> 3, c8 = idx & 7;
            uint32_t sw = (uint32_t)(r * 128 + ((c8 ^ (r & 7)) << 4));
            long long gb = (long long)r * 1280 + c8 * 8;
            cpa16(base + 16384 + sw, gBh + gb);
            cpa16(base + 24576 + sw, gBl + gb);
        }
        CPA_COMMIT();
    };

    load_chunk(0, 0);

    const int g = lane >> 3;
    for (int c = 0; c < nchunks; c++) {
        const int s = c & 1;
        if (c + 1 < nchunks) { load_chunk(c + 1, s ^ 1); CPA_WAIT1(); }
        else                 { CPA_WAIT0(); }
        __syncthreads();

        const uint32_t AB  = sb + s * STA_BYTES;
        const uint32_t BhB = AB + 16384;
        const uint32_t BlB = AB + 24576;

#pragma unroll
        for (int ks = 0; ks < 4; ks++) {
            uint32_t a[2][4], bh[4][2], bl[4][2];
#pragma unroll
            for (int mt = 0; mt < 2; mt++) {
                int ar = wm * 32 + mt * 16 + ((g & 1) << 3) + (lane & 7);
                int ac = ks * 2 + (g >> 1);
                uint32_t off = (uint32_t)(ar * 128 + ((ac ^ (ar & 7)) << 4));
                LDSM4(a[mt], AB + off);
            }
#pragma unroll
            for (int p = 0; p < 2; p++) {
                int br = wn * 32 + p * 16 + ((g >> 1) << 3) + (lane & 7);
                int bc = ks * 2 + (g & 1);
                uint32_t off = (uint32_t)(br * 128 + ((bc ^ (br & 7)) << 4));
                uint32_t t0[4], t1[4];
                LDSM4(t0, BhB + off);
                bh[2*p][0] = t0[0]; bh[2*p][1] = t0[1];
                bh[2*p+1][0] = t0[2]; bh[2*p+1][1] = t0[3];
                LDSM4(t1, BlB + off);
                bl[2*p][0] = t1[0]; bl[2*p][1] = t1[1];
                bl[2*p+1][0] = t1[2]; bl[2*p+1][1] = t1[3];
            }
#pragma unroll
            for (int mt = 0; mt < 2; mt++)
#pragma unroll
                for (int nt = 0; nt < 4; nt++) {
                    mma16816(acc[mt][nt], a[mt], bh[nt]);
                    mma16816(acc[mt][nt], a[mt], bl[nt]);
                }
        }
        __syncthreads();
    }

    const long long ldc = job.ldc;
    const int rbase = row0 + wm * 32;
    const int cbase = col0 + wn * 32;
#pragma unroll
    for (int nt = 0; nt < 4; nt++) {
        const int col = cbase + nt * 8 + ((lane & 3) << 1);
        float bv0 = 0.f, bv1 = 0.f;
        for (int sg = 0; sg < job.nseg; sg++) {
            const float* bp = job.seg[sg].bias;
            if (bp) { bv0 += bp[col]; bv1 += bp[col + 1]; }
        }
#pragma unroll
        for (int mt = 0; mt < 2; mt++) {
            const int r1 = rbase + mt * 16 + (lane >> 2);
            const int r2 = r1 + 8;
            const float* a4 = acc[mt][nt];
            if (job.mode == 1) {
                *(float2*)&job.C[(long long)r1 * ldc + col] = make_float2(a4[0] + bv0, a4[1] + bv1);
                *(float2*)&job.C[(long long)r2 * ldc + col] = make_float2(a4[2] + bv0, a4[3] + bv1);
            } else {
                *(__half2*)&job.Ch[(long long)r1 * ldc + col] =
                    __halves2half2(__float2half(a4[0] + bv0), __float2half(a4[1] + bv1));
                *(__half2*)&job.Ch[(long long)r2 * ldc + col] =
                    __halves2half2(__float2half(a4[2] + bv0), __float2half(a4[3] + bv1));
            }
        }
    }
}

// ================= kernel 2: 128x128 tiles (phases B0/B12/D — large M) ==========
// 256 threads, 8 warps (2x4 grid, warp tile 64x32), 2 CTAs/SM. (R11-proven)
#define ST_BYTES 49152
#define SMEM_TOTAL (2*ST_BYTES)

__global__ void __launch_bounds__(256, 2) mma_gemm(GBatch batch) {
    extern __shared__ char smem[];
    const GJob& job = batch.job[blockIdx.z];
    const uint32_t sb = smem_u32(smem);
    const int tid = threadIdx.x;
    const int lane = tid & 31, wid = tid >> 5;
    const int wm = wid & 1, wn = wid >> 1;          // 2x4 warp grid, warp tile 64x32
    const int row0 = blockIdx.y * 128;
    const int col0 = blockIdx.x * 128;

    float acc[4][4][4];
#pragma unroll
    for (int mt = 0; mt < 4; mt++)
#pragma unroll
        for (int nt = 0; nt < 4; nt++)
#pragma unroll
            for (int q = 0; q < 4; q++) acc[mt][nt][q] = 0.f;

    const int nchunks = job.nseg * 20;

    auto load_chunk = [&](int c, int s) {
        const int sg = c / 20, kc = c % 20;
        const GSeg& S = job.seg[sg];
        const uint32_t base = sb + s * ST_BYTES;
        const __half* gA  = S.A  + (long long)row0 * S.lda + kc * 64;
        const __half* gBh = S.Bh + (long long)col0 * 1280 + kc * 64;
        const __half* gBl = S.Bl + (long long)col0 * 1280 + kc * 64;
#pragma unroll
        for (int i = 0; i < 4; i++) {
            int idx = tid + i * 256;
            int r = idx >> 3, c8 = idx & 7;
            uint32_t sw = (uint32_t)(r * 128 + ((c8 ^ (r & 7)) << 4));
            cpa16(base + sw, gA + (long long)r * S.lda + c8 * 8);
        }
#pragma unroll
        for (int i = 0; i < 4; i++) {
            int idx = tid + i * 256;
            int r = idx >> 3, c8 = idx & 7;
            uint32_t sw = (uint32_t)(r * 128 + ((c8 ^ (r & 7)) << 4));
            long long gb = (long long)r * 1280 + c8 * 8;
            cpa16(base + 16384 + sw, gBh + gb);
            cpa16(base + 32768 + sw, gBl + gb);
        }
        CPA_COMMIT();
    };

    load_chunk(0, 0);

    const int g = lane >> 3;
    for (int c = 0; c < nchunks; c++) {
        const int s = c & 1;
        if (c + 1 < nchunks) { load_chunk(c + 1, s ^ 1); CPA_WAIT1(); }
        else                 { CPA_WAIT0(); }
        __syncthreads();

        const uint32_t AB  = sb + s * ST_BYTES;
        const uint32_t BhB = AB + 16384;
        const uint32_t BlB = AB + 32768;

#pragma unroll
        for (int ks = 0; ks < 4; ks++) {
            uint32_t bh[4][2], bl[4][2];
#pragma unroll
            for (int p = 0; p < 2; p++) {
                int br = wn * 32 + p * 16 + ((g >> 1) << 3) + (lane & 7);
                int bc = ks * 2 + (g & 1);
                uint32_t off = (uint32_t)(br * 128 + ((bc ^ (br & 7)) << 4));
                uint32_t t0[4], t1[4];
                LDSM4(t0, BhB + off);
                bh[2*p][0] = t0[0]; bh[2*p][1] = t0[1];
                bh[2*p+1][0] = t0[2]; bh[2*p+1][1] = t0[3];
                LDSM4(t1, BlB + off);
                bl[2*p][0] = t1[0]; bl[2*p][1] = t1[1];
                bl[2*p+1][0] = t1[2]; bl[2*p+1][1] = t1[3];
            }
#pragma unroll
            for (int mt = 0; mt < 4; mt++) {
                int ar = wm * 64 + mt * 16 + ((g & 1) << 3) + (lane & 7);
                int ac = ks * 2 + (g >> 1);
                uint32_t off = (uint32_t)(ar * 128 + ((ac ^ (ar & 7)) << 4));
                uint32_t a[4];
                LDSM4(a, AB + off);
#pragma unroll
                for (int nt = 0; nt < 4; nt++) {
                    mma16816(acc[mt][nt], a, bh[nt]);
                    mma16816(acc[mt][nt], a, bl[nt]);
                }
            }
        }
        __syncthreads();
    }

    const long long ldc = job.ldc;
    const int rbase = row0 + wm * 64;
    const int cbase = col0 + wn * 32;
#pragma unroll
    for (int nt = 0; nt < 4; nt++) {
        const int col = cbase + nt * 8 + ((lane & 3) << 1);
        float bv0 = 0.f, bv1 = 0.f;
        for (int sg = 0; sg < job.nseg; sg++) {
            const float* bp = job.seg[sg].bias;
            if (bp) { bv0 += bp[col]; bv1 += bp[col + 1]; }
        }
#pragma unroll
        for (int mt = 0; mt < 4; mt++) {
            const int r1 = rbase + mt * 16 + (lane >> 2);
            const int r2 = r1 + 8;
            const float* a4 = acc[mt][nt];
            if (job.mode == 1) {
                *(float2*)&job.C[(long long)r1 * ldc + col] = make_float2(a4[0] + bv0, a4[1] + bv1);
                *(float2*)&job.C[(long long)r2 * ldc + col] = make_float2(a4[2] + bv0, a4[3] + bv1);
            } else {
                *(__half2*)&job.Ch[(long long)r1 * ldc + col] =
                    __halves2half2(__float2half(a4[0] + bv0), __float2half(a4[1] + bv1));
                *(__half2*)&job.Ch[(long long)r2 * ldc + col] =
                    __halves2half2(__float2half(a4[2] + bv0), __float2half(a4[3] + bv1));
            }
        }
    }
}

// ---------------- weight transpose + fp16 split (once per call) -----------------
__global__ void wconv_k(const float* __restrict__ Win, const float* __restrict__ Wout,
                        const float* __restrict__ Wr, const float* __restrict__ Wz,
                        const float* __restrict__ Wt,
                        __half* __restrict__ wth, __half* __restrict__ wtl) {
    __shared__ float tile[32][33];
    const int slot = blockIdx.z;
    const int f0 = blockIdx.x * 32, d0 = blockIdx.y * 32;
    const float* base;
    if (slot < 6)       base = Win  + (long long)slot * DDLL;
    else if (slot < 12) base = Wout + (long long)(slot - 6) * DDLL;
    else {
        int gq = (slot - 12) / 3, q = (slot - 12) % 3;
        base = (gq == 0 ? Wr : (gq == 1 ? Wz : Wt)) + (long long)q * DDLL;
    }
    for (int i = threadIdx.y; i < 32; i += 8)
        tile[i][threadIdx.x] = base[(long long)(d0 + i) * 1280 + f0 + threadIdx.x];
    __syncthreads();
    __half* oh = wth + (long long)slot * DDLL;
    __half* ol = wtl + (long long)slot * DDLL;
    for (int i = threadIdx.y; i < 32; i += 8) {
        float v = tile[threadIdx.x][i];
        __half h, l; split2h(v, h, l);
        oh[(long long)(f0 + i) * 1280 + d0 + threadIdx.x] = h;
        ol[(long long)(f0 + i) * 1280 + d0 + threadIdx.x] = l;
    }
}

// ---------------- elementwise kernels ------------------------------------------
__global__ void copy_x_k(const float* __restrict__ x, float* __restrict__ gx,
                         __half* __restrict__ gf) {
    for (int i = blockIdx.x * blockDim.x + threadIdx.x; i < TOT; i += gridDim.x * blockDim.x) {
        float v = x[i]; gx[i] = v;
        gf[i] = __float2half(v);
    }
}

__global__ void zero_slices_k(__half* af, __half* of) {
    const int na[3] = {0, 4, 5};
    const int no[3] = {3, 4, 5};
    int total = 6 * B_ * D_;
    for (int idx = blockIdx.x * blockDim.x + threadIdx.x; idx < total;
         idx += gridDim.x * blockDim.x) {
        int s = idx / (B_ * D_);
        int r = idx % (B_ * D_);
        int b = r / D_, d = r % D_;
        __half z = __float2half(0.f);
        if (s < 3) af[((long long)b * N_ + na[s]) * D_ + d] = z;
        else       of[((long long)b * N_ + no[s - 3]) * D_ + d] = z;
    }
}

__global__ void sig_rgx_k(const float* __restrict__ prer, const float* __restrict__ gx,
                          __half* __restrict__ rf) {
    for (int i = blockIdx.x * blockDim.x + threadIdx.x; i < TOT; i += gridDim.x * blockDim.x) {
        float r = 1.f / (1.f + expf(-prer[i]));
        rf[i] = __float2half(r * gx[i]);
    }
}

__global__ void update_k(const float* __restrict__ prez, const float* __restrict__ pret,
                         const float* __restrict__ pretD, float* __restrict__ gx,
                         __half* __restrict__ gf) {
    for (int i = blockIdx.x * blockDim.x + threadIdx.x; i < TOT; i += gridDim.x * blockDim.x) {
        float z = 1.f / (1.f + expf(-prez[i]));
        float h = tanhf(pret[i] + pretD[i]);
        float gv = gx[i];
        float ng = gv + z * (h - gv);
        gx[i] = ng;
        gf[i] = __float2half(ng);
    }
}

__global__ void transpose_k(const float* __restrict__ gx, float* __restrict__ out) {
    for (int idx = blockIdx.x * blockDim.x + threadIdx.x; idx < TOT;
         idx += gridDim.x * blockDim.x) {
        int b = idx / (N_ * D_);
        int r = idx % (N_ * D_);
        int d = r / N_, n = r % N_;
        out[idx] = gx[((long long)b * N_ + n) * D_ + d];
    }
}

// ---------------- host orchestration ------------------------------------------
extern "C" void kernel_launch(void* const* d_in, const int* in_sizes, int n_in,
                              void* d_out, int out_size) {
    const float* x     = (const float*)d_in[0];
    const float* W_in  = (const float*)d_in[2];
    const float* b_in  = (const float*)d_in[3];
    const float* W_out = (const float*)d_in[4];
    const float* b_out = (const float*)d_in[5];
    const float* W_r   = (const float*)d_in[6];
    const float* b_r   = (const float*)d_in[7];
    const float* W_z   = (const float*)d_in[8];
    const float* b_z   = (const float*)d_in[9];
    const float* W_t   = (const float*)d_in[10];
    const float* b_t   = (const float*)d_in[11];
    float* out = (float*)d_out;

    float *gx, *prer, *prez, *pret, *pretD;
    __half *gxf, *ainf, *aoutf, *rgxf, *wth, *wtl;
    cudaGetSymbolAddress((void**)&gx,    g_gx);
    cudaGetSymbolAddress((void**)&prer,  g_prer);
    cudaGetSymbolAddress((void**)&prez,  g_prez);
    cudaGetSymbolAddress((void**)&pret,  g_pret);
    cudaGetSymbolAddress((void**)&pretD, g_pretD);
    cudaGetSymbolAddress((void**)&gxf,   g_gxf);
    cudaGetSymbolAddress((void**)&ainf,  g_ainf);
    cudaGetSymbolAddress((void**)&aoutf, g_aoutf);
    cudaGetSymbolAddress((void**)&rgxf,  g_rgxf);
    cudaGetSymbolAddress((void**)&wth,   g_wth);
    cudaGetSymbolAddress((void**)&wtl,   g_wtl);

    cudaFuncSetAttribute(mma_gemm,  cudaFuncAttributeMaxDynamicSharedMemorySize, SMEM_TOTAL);
    cudaFuncSetAttribute(mma_gemmA, cudaFuncAttributeMaxDynamicSharedMemorySize, SMEM_A_TOTAL);

    // side stream + events (created once; host-side resources only)
    static cudaStream_t s1 = nullptr;
    static cudaEvent_t evFork = nullptr, evJoin = nullptr;
    if (!s1) {
        cudaStreamCreateWithFlags(&s1, cudaStreamNonBlocking);
        cudaEventCreateWithFlags(&evFork, cudaEventDisableTiming);
        cudaEventCreateWithFlags(&evJoin, cudaEventDisableTiming);
    }

    const long long ldn = (long long)N_ * D_;
    auto wslot = [&](int s) { return (long long)s * DDLL; };

    // ---- Phase A (mode 0): edge propagation ----
    GBatch bA = {};
    {
        auto seg_in = [&](int src, int et) {
            GSeg s{};
            s.A = gxf + (long long)src * D_; s.lda = ldn;
            s.Bh = wth + wslot(et); s.Bl = wtl + wslot(et);
            s.bias = b_in + (long long)et * D_;
            return s;
        };
        auto seg_out = [&](int tgt, int et) {
            GSeg s{};
            s.A = gxf + (long long)tgt * D_; s.lda = ldn;
            s.Bh = wth + wslot(6 + et); s.Bl = wtl + wslot(6 + et);
            s.bias = b_out + (long long)et * D_;
            return s;
        };
        auto setC = [&](GJob& j, __half* cf, int node) {
            j.Ch = cf + (long long)node * D_;
            j.ldc = ldn; j.mode = 0;
        };
        bA.job[0].seg[0] = seg_in(0, 2); bA.job[0].seg[1] = seg_in(1, 4); bA.job[0].seg[2] = seg_in(2, 5);
        bA.job[0].nseg = 3; setC(bA.job[0], ainf, 3);
        bA.job[1].seg[0] = seg_out(1, 0); bA.job[1].seg[1] = seg_out(2, 1); bA.job[1].seg[2] = seg_out(3, 2);
        bA.job[1].nseg = 3; setC(bA.job[1], aoutf, 0);
        bA.job[2].seg[0] = seg_in(0, 1); bA.job[2].seg[1] = seg_in(1, 3);
        bA.job[2].nseg = 2; setC(bA.job[2], ainf, 2);
        bA.job[3].seg[0] = seg_out(2, 3); bA.job[3].seg[1] = seg_out(3, 4);
        bA.job[3].nseg = 2; setC(bA.job[3], aoutf, 1);
        bA.job[4].seg[0] = seg_in(0, 0); bA.job[4].nseg = 1; setC(bA.job[4], ainf, 1);
        bA.job[5].seg[0] = seg_out(3, 5); bA.job[5].nseg = 1; setC(bA.job[5], aoutf, 2);
    }

    auto mkseg = [&](const __half* A, int gslot, const float* bias) {
        GSeg s{};
        s.A = A; s.lda = D_;
        s.Bh = wth + wslot(gslot); s.Bl = wtl + wslot(gslot);
        s.bias = bias;
        return s;
    };

    // ---- Phase B0 (mode 1): prer only ----
    GBatch bB0 = {};
    bB0.job[0].seg[0] = mkseg(ainf, 12, b_r);
    bB0.job[0].seg[1] = mkseg(aoutf, 13, 0);
    bB0.job[0].seg[2] = mkseg(gxf, 14, 0);
    bB0.job[0].nseg = 3; bB0.job[0].C = prer; bB0.job[0].ldc = D_; bB0.job[0].mode = 1;

    // ---- Phase B12 (mode 1): prez, pret-partial ----
    GBatch bB12 = {};
    bB12.job[0].seg[0] = mkseg(ainf, 15, b_z);
    bB12.job[0].seg[1] = mkseg(aoutf, 16, 0);
    bB12.job[0].seg[2] = mkseg(gxf, 17, 0);
    bB12.job[0].nseg = 3; bB12.job[0].C = prez; bB12.job[0].ldc = D_; bB12.job[0].mode = 1;
    bB12.job[1].seg[0] = mkseg(ainf, 18, b_t);
    bB12.job[1].seg[1] = mkseg(aoutf, 19, 0);
    bB12.job[1].nseg = 2; bB12.job[1].C = pret; bB12.job[1].ldc = D_; bB12.job[1].mode = 1;

    // ---- Phase D (mode 1): pretD = (r*gx) @ Wt2 ----
    GBatch bD = {};
    {
        GSeg s{};
        s.A = rgxf; s.lda = D_;
        s.Bh = wth + wslot(20); s.Bl = wtl + wslot(20); s.bias = 0;
        bD.job[0].seg[0] = s; bD.job[0].nseg = 1;
        bD.job[0].C = pretD; bD.job[0].ldc = D_; bD.job[0].mode = 1;
    }

    // ---- run ----
    wconv_k<<<dim3(40, 40, 21), dim3(32, 8)>>>(W_in, W_out, W_r, W_z, W_t, wth, wtl);
    copy_x_k<<<2048, 256>>>(x, gx, gxf);
    zero_slices_k<<<2048, 256>>>(ainf, aoutf);

    for (int step = 0; step < STEPS_; step++) {
        mma_gemmA<<<dim3(20, 8, 6),  256, SMEM_A_TOTAL>>>(bA);  // edges (128x64 tiles)
        mma_gemm<<<dim3(10, 48, 1), 256, SMEM_TOTAL>>>(bB0);    // prer (128x128 tiles)
        cudaEventRecord(evFork, 0);
        cudaStreamWaitEvent(s1, evFork, 0);
        sig_rgx_k<<<2048, 256, 0, s1>>>(prer, gx, rgxf);                 // side stream
        mma_gemm<<<dim3(10, 48, 1), 256, SMEM_TOTAL, s1>>>(bD);          // pretD
        cudaEventRecord(evJoin, s1);
        mma_gemm<<<dim3(10, 48, 2), 256, SMEM_TOTAL>>>(bB12);   // prez, pret (overlaps side)
        cudaStreamWaitEvent(0, evJoin, 0);
        update_k<<<2048, 256>>>(prez, pret, pretD, gx, gxf);
    }
    transpose_k<<<2048, 256>>>(gx, out);
}

// round 14
// speedup vs baseline: 1.3578x; 1.3150x over previous
#include <cuda_runtime.h>
#include <cuda_bf16.h>
#include <cuda_fp16.h>
#include <cstdint>
#include <math.h>

#define B_ 1024
#define N_ 6
#define D_ 1280
#define STEPS_ 5
#define TOT (B_*N_*D_)
#define BD ((long long)B_*D_)
#define DDLL (1280LL*1280LL)

// ---------------- scratch (static device globals; no allocations) -------------
// All activation buffers are NODE-MAJOR: index (n*B + b)*D + d
__device__ float g_gx [TOT];
__device__ float g_prer[TOT];
__device__ float g_prez[TOT];
__device__ float g_pret[TOT];
__device__ float g_pretD[TOT];
__device__ __half g_gxf [TOT];
__device__ __half g_ainf[TOT];
__device__ __half g_aoutf[TOT];
__device__ __half g_rgxf[TOT];
// 21 transposed weight matrices (1280x1280), fp16 hi/lo (22-bit effective)
__device__ __half g_wth[21u*1280u*1280u];
__device__ __half g_wtl[21u*1280u*1280u];

// ---------------- PTX helpers (stable ISA only) --------------------------------
__device__ __forceinline__ uint32_t smem_u32(const void* p) {
    uint32_t a;
    asm("{ .reg .u64 t; cvta.to.shared.u64 t, %1; cvt.u32.u64 %0, t; }" : "=r"(a) : "l"(p));
    return a;
}
__device__ __forceinline__ void cpa16(uint32_t dst, const void* src) {
    asm volatile("cp.async.cg.shared.global [%0], [%1], 16;" :: "r"(dst), "l"(src));
}
#define CPA_COMMIT() asm volatile("cp.async.commit_group;" ::: "memory")
#define CPA_WAIT1()  asm volatile("cp.async.wait_group 1;" ::: "memory")
#define CPA_WAIT0()  asm volatile("cp.async.wait_group 0;" ::: "memory")

#define LDSM4(r, a) \
    asm volatile("ldmatrix.sync.aligned.m8n8.x4.shared.b16 {%0,%1,%2,%3}, [%4];" \
        : "=r"((r)[0]), "=r"((r)[1]), "=r"((r)[2]), "=r"((r)[3]) : "r"(a))

__device__ __forceinline__ void mma16816(float* c, const uint32_t* a, const uint32_t* b) {
    asm volatile("mma.sync.aligned.m16n8k16.row.col.f32.f16.f16.f32 "
        "{%0,%1,%2,%3}, {%4,%5,%6,%7}, {%8,%9}, {%0,%1,%2,%3};"
        : "+f"(c[0]), "+f"(c[1]), "+f"(c[2]), "+f"(c[3])
        : "r"(a[0]), "r"(a[1]), "r"(a[2]), "r"(a[3]), "r"(b[0]), "r"(b[1]));
}

__device__ __forceinline__ void split2h(float v, __half& h, __half& l) {
    h = __float2half(v);
    l = __float2half(v - __half2float(h));
}

// ---------------- shared job structs --------------------------------------------
struct GSeg {
    const __half* A;
    const __half* Bh; const __half* Bl;   // W transposed [n][k]
    const float* bias; long long lda;
};
struct GJob {
    GSeg seg[3];
    float* C; __half* Ch;
    long long ldc; int nseg; int mode;    // 0: fp16 out (+bias); 1: fp32 out (+bias)
    int M;                                 // rows in this job (blocks beyond exit)
};
struct GBatch { GJob job[8]; };

// ================= kernel 1: 128x64 tiles (phase A — small M, uneven jobs) ======
#define STA_BYTES 32768
#define SMEM_A_TOTAL (2*STA_BYTES)

__global__ void __launch_bounds__(256, 2) mma_gemmA(GBatch batch) {
    extern __shared__ char smem[];
    const GJob& job = batch.job[blockIdx.z];
    const int row0 = blockIdx.y * 128;
    if (row0 >= job.M) return;
    const uint32_t sb = smem_u32(smem);
    const int tid = threadIdx.x;
    const int lane = tid & 31, wid = tid >> 5;
    const int wm = wid & 3, wn = wid >> 2;          // 4x2 warp grid, warp tile 32x32
    const int col0 = blockIdx.x * 64;

    float acc[2][4][4];
#pragma unroll
    for (int mt = 0; mt < 2; mt++)
#pragma unroll
        for (int nt = 0; nt < 4; nt++)
#pragma unroll
            for (int q = 0; q < 4; q++) acc[mt][nt][q] = 0.f;

    const int nchunks = job.nseg * 20;

    auto load_chunk = [&](int c, int s) {
        const int sg = c / 20, kc = c % 20;
        const GSeg& S = job.seg[sg];
        const uint32_t base = sb + s * STA_BYTES;
        const __half* gA  = S.A  + (long long)row0 * S.lda + kc * 64;
        const __half* gBh = S.Bh + (long long)col0 * 1280 + kc * 64;
        const __half* gBl = S.Bl + (long long)col0 * 1280 + kc * 64;
#pragma unroll
        for (int i = 0; i < 4; i++) {
            int idx = tid + i * 256;
            int r = idx >> 3, c8 = idx & 7;
            uint32_t sw = (uint32_t)(r * 128 + ((c8 ^ (r & 7)) << 4));
            cpa16(base + sw, gA + (long long)r * S.lda + c8 * 8);
        }
#pragma unroll
        for (int i = 0; i < 2; i++) {
            int idx = tid + i * 256;
            int r = idx >> 3, c8 = idx & 7;
            uint32_t sw = (uint32_t)(r * 128 + ((c8 ^ (r & 7)) << 4));
            long long gb = (long long)r * 1280 + c8 * 8;
            cpa16(base + 16384 + sw, gBh + gb);
            cpa16(base + 24576 + sw, gBl + gb);
        }
        CPA_COMMIT();
    };

    load_chunk(0, 0);

    const int g = lane >> 3;
    for (int c = 0; c < nchunks; c++) {
        const int s = c & 1;
        if (c + 1 < nchunks) { load_chunk(c + 1, s ^ 1); CPA_WAIT1(); }
        else                 { CPA_WAIT0(); }
        __syncthreads();

        const uint32_t AB  = sb + s * STA_BYTES;
        const uint32_t BhB = AB + 16384;
        const uint32_t BlB = AB + 24576;

#pragma unroll
        for (int ks = 0; ks < 4; ks++) {
            uint32_t a[2][4], bh[4][2], bl[4][2];
#pragma unroll
            for (int mt = 0; mt < 2; mt++) {
                int ar = wm * 32 + mt * 16 + ((g & 1) << 3) + (lane & 7);
                int ac = ks * 2 + (g >> 1);
                uint32_t off = (uint32_t)(ar * 128 + ((ac ^ (ar & 7)) << 4));
                LDSM4(a[mt], AB + off);
            }
#pragma unroll
            for (int p = 0; p < 2; p++) {
                int br = wn * 32 + p * 16 + ((g >> 1) << 3) + (lane & 7);
                int bc = ks * 2 + (g & 1);
                uint32_t off = (uint32_t)(br * 128 + ((bc ^ (br & 7)) << 4));
                uint32_t t0[4], t1[4];
                LDSM4(t0, BhB + off);
                bh[2*p][0] = t0[0]; bh[2*p][1] = t0[1];
                bh[2*p+1][0] = t0[2]; bh[2*p+1][1] = t0[3];
                LDSM4(t1, BlB + off);
                bl[2*p][0] = t1[0]; bl[2*p][1] = t1[1];
                bl[2*p+1][0] = t1[2]; bl[2*p+1][1] = t1[3];
            }
#pragma unroll
            for (int mt = 0; mt < 2; mt++)
#pragma unroll
                for (int nt = 0; nt < 4; nt++) {
                    mma16816(acc[mt][nt], a[mt], bh[nt]);
                    mma16816(acc[mt][nt], a[mt], bl[nt]);
                }
        }
        __syncthreads();
    }

    const long long ldc = job.ldc;
    const int rbase = row0 + wm * 32;
    const int cbase = col0 + wn * 32;
#pragma unroll
    for (int nt = 0; nt < 4; nt++) {
        const int col = cbase + nt * 8 + ((lane & 3) << 1);
        float bv0 = 0.f, bv1 = 0.f;
        for (int sg = 0; sg < job.nseg; sg++) {
            const float* bp = job.seg[sg].bias;
            if (bp) { bv0 += bp[col]; bv1 += bp[col + 1]; }
        }
#pragma unroll
        for (int mt = 0; mt < 2; mt++) {
            const int r1 = rbase + mt * 16 + (lane >> 2);
            const int r2 = r1 + 8;
            const float* a4 = acc[mt][nt];
            if (job.mode == 1) {
                *(float2*)&job.C[(long long)r1 * ldc + col] = make_float2(a4[0] + bv0, a4[1] + bv1);
                *(float2*)&job.C[(long long)r2 * ldc + col] = make_float2(a4[2] + bv0, a4[3] + bv1);
            } else {
                *(__half2*)&job.Ch[(long long)r1 * ldc + col] =
                    __halves2half2(__float2half(a4[0] + bv0), __float2half(a4[1] + bv1));
                *(__half2*)&job.Ch[(long long)r2 * ldc + col] =
                    __halves2half2(__float2half(a4[2] + bv0), __float2half(a4[3] + bv1));
            }
        }
    }
}

// ================= kernel 2: 128x128 tiles (gate phases — large M) ==============
#define ST_BYTES 49152
#define SMEM_TOTAL (2*ST_BYTES)

__global__ void __launch_bounds__(256, 2) mma_gemm(GBatch batch) {
    extern __shared__ char smem[];
    const GJob& job = batch.job[blockIdx.z];
    const int row0 = blockIdx.y * 128;
    if (row0 >= job.M) return;
    const uint32_t sb = smem_u32(smem);
    const int tid = threadIdx.x;
    const int lane = tid & 31, wid = tid >> 5;
    const int wm = wid & 1, wn = wid >> 1;          // 2x4 warp grid, warp tile 64x32
    const int col0 = blockIdx.x * 128;

    float acc[4][4][4];
#pragma unroll
    for (int mt = 0; mt < 4; mt++)
#pragma unroll
        for (int nt = 0; nt < 4; nt++)
#pragma unroll
            for (int q = 0; q < 4; q++) acc[mt][nt][q] = 0.f;

    const int nchunks = job.nseg * 20;

    auto load_chunk = [&](int c, int s) {
        const int sg = c / 20, kc = c % 20;
        const GSeg& S = job.seg[sg];
        const uint32_t base = sb + s * ST_BYTES;
        const __half* gA  = S.A  + (long long)row0 * S.lda + kc * 64;
        const __half* gBh = S.Bh + (long long)col0 * 1280 + kc * 64;
        const __half* gBl = S.Bl + (long long)col0 * 1280 + kc * 64;
#pragma unroll
        for (int i = 0; i < 4; i++) {
            int idx = tid + i * 256;
            int r = idx >> 3, c8 = idx & 7;
            uint32_t sw = (uint32_t)(r * 128 + ((c8 ^ (r & 7)) << 4));
            cpa16(base + sw, gA + (long long)r * S.lda + c8 * 8);
        }
#pragma unroll
        for (int i = 0; i < 4; i++) {
            int idx = tid + i * 256;
            int r = idx >> 3, c8 = idx & 7;
            uint32_t sw = (uint32_t)(r * 128 + ((c8 ^ (r & 7)) << 4));
            long long gb = (long long)r * 1280 + c8 * 8;
            cpa16(base + 16384 + sw, gBh + gb);
            cpa16(base + 32768 + sw, gBl + gb);
        }
        CPA_COMMIT();
    };

    load_chunk(0, 0);

    const int g = lane >> 3;
    for (int c = 0; c < nchunks; c++) {
        const int s = c & 1;
        if (c + 1 < nchunks) { load_chunk(c + 1, s ^ 1); CPA_WAIT1(); }
        else                 { CPA_WAIT0(); }
        __syncthreads();

        const uint32_t AB  = sb + s * ST_BYTES;
        const uint32_t BhB = AB + 16384;
        const uint32_t BlB = AB + 32768;

#pragma unroll
        for (int ks = 0; ks < 4; ks++) {
            uint32_t bh[4][2], bl[4][2];
#pragma unroll
            for (int p = 0; p < 2; p++) {
                int br = wn * 32 + p * 16 + ((g >> 1) << 3) + (lane & 7);
                int bc = ks * 2 + (g & 1);
                uint32_t off = (uint32_t)(br * 128 + ((bc ^ (br & 7)) << 4));
                uint32_t t0[4], t1[4];
                LDSM4(t0, BhB + off);
                bh[2*p][0] = t0[0]; bh[2*p][1] = t0[1];
                bh[2*p+1][0] = t0[2]; bh[2*p+1][1] = t0[3];
                LDSM4(t1, BlB + off);
                bl[2*p][0] = t1[0]; bl[2*p][1] = t1[1];
                bl[2*p+1][0] = t1[2]; bl[2*p+1][1] = t1[3];
            }
#pragma unroll
            for (int mt = 0; mt < 4; mt++) {
                int ar = wm * 64 + mt * 16 + ((g & 1) << 3) + (lane & 7);
                int ac = ks * 2 + (g >> 1);
                uint32_t off = (uint32_t)(ar * 128 + ((ac ^ (ar & 7)) << 4));
                uint32_t a[4];
                LDSM4(a, AB + off);
#pragma unroll
                for (int nt = 0; nt < 4; nt++) {
                    mma16816(acc[mt][nt], a, bh[nt]);
                    mma16816(acc[mt][nt], a, bl[nt]);
                }
            }
        }
        __syncthreads();
    }

    const long long ldc = job.ldc;
    const int rbase = row0 + wm * 64;
    const int cbase = col0 + wn * 32;
#pragma unroll
    for (int nt = 0; nt < 4; nt++) {
        const int col = cbase + nt * 8 + ((lane & 3) << 1);
        float bv0 = 0.f, bv1 = 0.f;
        for (int sg = 0; sg < job.nseg; sg++) {
            const float* bp = job.seg[sg].bias;
            if (bp) { bv0 += bp[col]; bv1 += bp[col + 1]; }
        }
#pragma unroll
        for (int mt = 0; mt < 4; mt++) {
            const int r1 = rbase + mt * 16 + (lane >> 2);
            const int r2 = r1 + 8;
            const float* a4 = acc[mt][nt];
            if (job.mode == 1) {
                *(float2*)&job.C[(long long)r1 * ldc + col] = make_float2(a4[0] + bv0, a4[1] + bv1);
                *(float2*)&job.C[(long long)r2 * ldc + col] = make_float2(a4[2] + bv0, a4[3] + bv1);
            } else {
                *(__half2*)&job.Ch[(long long)r1 * ldc + col] =
                    __halves2half2(__float2half(a4[0] + bv0), __float2half(a4[1] + bv1));
                *(__half2*)&job.Ch[(long long)r2 * ldc + col] =
                    __halves2half2(__float2half(a4[2] + bv0), __float2half(a4[3] + bv1));
            }
        }
    }
}

// ---------------- weight transpose + fp16 split (once per call) -----------------
__global__ void wconv_k(const float* __restrict__ Win, const float* __restrict__ Wout,
                        const float* __restrict__ Wr, const float* __restrict__ Wz,
                        const float* __restrict__ Wt,
                        __half* __restrict__ wth, __half* __restrict__ wtl) {
    __shared__ float tile[32][33];
    const int slot = blockIdx.z;
    const int f0 = blockIdx.x * 32, d0 = blockIdx.y * 32;
    const float* base;
    if (slot < 6)       base = Win  + (long long)slot * DDLL;
    else if (slot < 12) base = Wout + (long long)(slot - 6) * DDLL;
    else {
        int gq = (slot - 12) / 3, q = (slot - 12) % 3;
        base = (gq == 0 ? Wr : (gq == 1 ? Wz : Wt)) + (long long)q * DDLL;
    }
    for (int i = threadIdx.y; i < 32; i += 8)
        tile[i][threadIdx.x] = base[(long long)(d0 + i) * 1280 + f0 + threadIdx.x];
    __syncthreads();
    __half* oh = wth + (long long)slot * DDLL;
    __half* ol = wtl + (long long)slot * DDLL;
    for (int i = threadIdx.y; i < 32; i += 8) {
        float v = tile[threadIdx.x][i];
        __half h, l; split2h(v, h, l);
        oh[(long long)(f0 + i) * 1280 + d0 + threadIdx.x] = h;
        ol[(long long)(f0 + i) * 1280 + d0 + threadIdx.x] = l;
    }
}

// ---------------- elementwise kernels (node-major) ------------------------------
// x is [b][n][d]; internal buffers are [n][b][d]
__global__ void copy_x_k(const float* __restrict__ x, float* __restrict__ gx,
                         __half* __restrict__ gf) {
    for (long long j = blockIdx.x * blockDim.x + threadIdx.x; j < TOT;
         j += (long long)gridDim.x * blockDim.x) {
        int n = (int)(j / BD);
        long long rem = j - (long long)n * BD;
        int b = (int)(rem / D_), d = (int)(rem % D_);
        float v = x[((long long)b * N_ + n) * D_ + d];
        gx[j] = v;
        gf[j] = __float2half(v);
    }
}

__global__ void sig_rgx_k(const float* __restrict__ prer, const float* __restrict__ gx,
                          __half* __restrict__ rf) {
    for (int i = blockIdx.x * blockDim.x + threadIdx.x; i < TOT; i += gridDim.x * blockDim.x) {
        float r = 1.f / (1.f + expf(-prer[i]));
        rf[i] = __float2half(r * gx[i]);
    }
}

__global__ void update_k(const float* __restrict__ prez, const float* __restrict__ pret,
                         const float* __restrict__ pretD, const float* __restrict__ b_t,
                         float* __restrict__ gx, __half* __restrict__ gf) {
    const long long lim = 4LL * BD;   // nodes 4,5 have no pret GEMM: pret = b_t only
    for (long long i = blockIdx.x * blockDim.x + threadIdx.x; i < TOT;
         i += (long long)gridDim.x * blockDim.x) {
        float pt = (i < lim) ? pret[i] : b_t[(int)(i % D_)];
        float z = 1.f / (1.f + expf(-prez[i]));
        float h = tanhf(pt + pretD[i]);
        float gv = gx[i];
        float ng = gv + z * (h - gv);
        gx[i] = ng;
        gf[i] = __float2half(ng);
    }
}

// out[b, d*N + n] = gx[(n*B+b)*D + d]
__global__ void transpose_k(const float* __restrict__ gx, float* __restrict__ out) {
    for (long long idx = blockIdx.x * blockDim.x + threadIdx.x; idx < TOT;
         idx += (long long)gridDim.x * blockDim.x) {
        int b = (int)(idx / ((long long)N_ * D_));
        long long r = idx - (long long)b * N_ * D_;
        int d = (int)(r / N_), n = (int)(r % N_);
        out[idx] = gx[((long long)n * B_ + b) * D_ + d];
    }
}

// ---------------- host orchestration ------------------------------------------
extern "C" void kernel_launch(void* const* d_in, const int* in_sizes, int n_in,
                              void* d_out, int out_size) {
    const float* x     = (const float*)d_in[0];
    const float* W_in  = (const float*)d_in[2];
    const float* b_in  = (const float*)d_in[3];
    const float* W_out = (const float*)d_in[4];
    const float* b_out = (const float*)d_in[5];
    const float* W_r   = (const float*)d_in[6];
    const float* b_r   = (const float*)d_in[7];
    const float* W_z   = (const float*)d_in[8];
    const float* b_z   = (const float*)d_in[9];
    const float* W_t   = (const float*)d_in[10];
    const float* b_t   = (const float*)d_in[11];
    float* out = (float*)d_out;

    float *gx, *prer, *prez, *pret, *pretD;
    __half *gxf, *ainf, *aoutf, *rgxf, *wth, *wtl;
    cudaGetSymbolAddress((void**)&gx,    g_gx);
    cudaGetSymbolAddress((void**)&prer,  g_prer);
    cudaGetSymbolAddress((void**)&prez,  g_prez);
    cudaGetSymbolAddress((void**)&pret,  g_pret);
    cudaGetSymbolAddress((void**)&pretD, g_pretD);
    cudaGetSymbolAddress((void**)&gxf,   g_gxf);
    cudaGetSymbolAddress((void**)&ainf,  g_ainf);
    cudaGetSymbolAddress((void**)&aoutf, g_aoutf);
    cudaGetSymbolAddress((void**)&rgxf,  g_rgxf);
    cudaGetSymbolAddress((void**)&wth,   g_wth);
    cudaGetSymbolAddress((void**)&wtl,   g_wtl);

    cudaFuncSetAttribute(mma_gemm,  cudaFuncAttributeMaxDynamicSharedMemorySize, SMEM_TOTAL);
    cudaFuncSetAttribute(mma_gemmA, cudaFuncAttributeMaxDynamicSharedMemorySize, SMEM_A_TOTAL);

    static cudaStream_t s1 = nullptr;
    static cudaEvent_t evFork = nullptr, evJoin = nullptr;
    if (!s1) {
        cudaStreamCreateWithFlags(&s1, cudaStreamNonBlocking);
        cudaEventCreateWithFlags(&evFork, cudaEventDisableTiming);
        cudaEventCreateWithFlags(&evJoin, cudaEventDisableTiming);
    }

    auto wslot = [&](int s) { return (long long)s * DDLL; };

    // ---- Phase A (mode 0): edge propagation, node-major, lda = D ----
    GBatch bA = {};
    {
        auto seg_in = [&](int src, int et) {
            GSeg s{};
            s.A = gxf + (long long)src * BD; s.lda = D_;
            s.Bh = wth + wslot(et); s.Bl = wtl + wslot(et);
            s.bias = b_in + (long long)et * D_;
            return s;
        };
        auto seg_out = [&](int tgt, int et) {
            GSeg s{};
            s.A = gxf + (long long)tgt * BD; s.lda = D_;
            s.Bh = wth + wslot(6 + et); s.Bl = wtl + wslot(6 + et);
            s.bias = b_out + (long long)et * D_;
            return s;
        };
        auto setC = [&](GJob& j, __half* cf, int node) {
            j.Ch = cf + (long long)node * BD;
            j.ldc = D_; j.mode = 0; j.M = B_;
        };
        bA.job[0].seg[0] = seg_in(0, 2); bA.job[0].seg[1] = seg_in(1, 4); bA.job[0].seg[2] = seg_in(2, 5);
        bA.job[0].nseg = 3; setC(bA.job[0], ainf, 3);
        bA.job[1].seg[0] = seg_out(1, 0); bA.job[1].seg[1] = seg_out(2, 1); bA.job[1].seg[2] = seg_out(3, 2);
        bA.job[1].nseg = 3; setC(bA.job[1], aoutf, 0);
        bA.job[2].seg[0] = seg_in(0, 1); bA.job[2].seg[1] = seg_in(1, 3);
        bA.job[2].nseg = 2; setC(bA.job[2], ainf, 2);
        bA.job[3].seg[0] = seg_out(2, 3); bA.job[3].seg[1] = seg_out(3, 4);
        bA.job[3].nseg = 2; setC(bA.job[3], aoutf, 1);
        bA.job[4].seg[0] = seg_in(0, 0); bA.job[4].nseg = 1; setC(bA.job[4], ainf, 1);
        bA.job[5].seg[0] = seg_out(3, 5); bA.job[5].nseg = 1; setC(bA.job[5], aoutf, 2);
    }

    // segment maker: activation buffer + node offset, gate weight slot, bias
    auto mkseg = [&](const __half* A, int node, int gslot, const float* bias) {
        GSeg s{};
        s.A = A + (long long)node * BD; s.lda = D_;
        s.Bh = wth + wslot(gslot); s.Bl = wtl + wslot(gslot);
        s.bias = bias;
        return s;
    };
    // gate weight slots: Wr blocks 12(ain),13(aout),14(gx); Wz 15,16,17; Wt 18,19,20

    // ---- R launch: prer by node group (skip zero segments) ----
    // ain==0 for nodes {0,4,5}; aout==0 for nodes {3,4,5}
    GBatch bR = {};
    // r12: nodes 1-2 (all three segs)
    bR.job[0].seg[0] = mkseg(ainf, 1, 12, b_r);
    bR.job[0].seg[1] = mkseg(aoutf, 1, 13, 0);
    bR.job[0].seg[2] = mkseg(gxf, 1, 14, 0);
    bR.job[0].nseg = 3; bR.job[0].C = prer + BD; bR.job[0].ldc = D_; bR.job[0].mode = 1; bR.job[0].M = 2 * B_;
    // r45: nodes 4-5 (gx only)
    bR.job[1].seg[0] = mkseg(gxf, 4, 14, b_r);
    bR.job[1].nseg = 1; bR.job[1].C = prer + 4 * BD; bR.job[1].ldc = D_; bR.job[1].mode = 1; bR.job[1].M = 2 * B_;
    // r0: node 0 (aout, gx)
    bR.job[2].seg[0] = mkseg(aoutf, 0, 13, b_r);
    bR.job[2].seg[1] = mkseg(gxf, 0, 14, 0);
    bR.job[2].nseg = 2; bR.job[2].C = prer; bR.job[2].ldc = D_; bR.job[2].mode = 1; bR.job[2].M = B_;
    // r3: node 3 (ain, gx)
    bR.job[3].seg[0] = mkseg(ainf, 3, 12, b_r);
    bR.job[3].seg[1] = mkseg(gxf, 3, 14, 0);
    bR.job[3].nseg = 2; bR.job[3].C = prer + 3 * BD; bR.job[3].ldc = D_; bR.job[3].mode = 1; bR.job[3].M = B_;

    // ---- ZT launch: prez (4 jobs) + pret partial (3 jobs) ----
    GBatch bZT = {};
    bZT.job[0].seg[0] = mkseg(ainf, 1, 15, b_z);
    bZT.job[0].seg[1] = mkseg(aoutf, 1, 16, 0);
    bZT.job[0].seg[2] = mkseg(gxf, 1, 17, 0);
    bZT.job[0].nseg = 3; bZT.job[0].C = prez + BD; bZT.job[0].ldc = D_; bZT.job[0].mode = 1; bZT.job[0].M = 2 * B_;
    bZT.job[1].seg[0] = mkseg(gxf, 4, 17, b_z);
    bZT.job[1].nseg = 1; bZT.job[1].C = prez + 4 * BD; bZT.job[1].ldc = D_; bZT.job[1].mode = 1; bZT.job[1].M = 2 * B_;
    bZT.job[2].seg[0] = mkseg(ainf, 1, 18, b_t);
    bZT.job[2].seg[1] = mkseg(aoutf, 1, 19, 0);
    bZT.job[2].nseg = 2; bZT.job[2].C = pret + BD; bZT.job[2].ldc = D_; bZT.job[2].mode = 1; bZT.job[2].M = 2 * B_;
    bZT.job[3].seg[0] = mkseg(aoutf, 0, 16, b_z);
    bZT.job[3].seg[1] = mkseg(gxf, 0, 17, 0);
    bZT.job[3].nseg = 2; bZT.job[3].C = prez; bZT.job[3].ldc = D_; bZT.job[3].mode = 1; bZT.job[3].M = B_;
    bZT.job[4].seg[0] = mkseg(ainf, 3, 15, b_z);
    bZT.job[4].seg[1] = mkseg(gxf, 3, 17, 0);
    bZT.job[4].nseg = 2; bZT.job[4].C = prez + 3 * BD; bZT.job[4].ldc = D_; bZT.job[4].mode = 1; bZT.job[4].M = B_;
    bZT.job[5].seg[0] = mkseg(aoutf, 0, 19, b_t);
    bZT.job[5].nseg = 1; bZT.job[5].C = pret; bZT.job[5].ldc = D_; bZT.job[5].mode = 1; bZT.job[5].M = B_;
    bZT.job[6].seg[0] = mkseg(ainf, 3, 18, b_t);
    bZT.job[6].nseg = 1; bZT.job[6].C = pret + 3 * BD; bZT.job[6].ldc = D_; bZT.job[6].mode = 1; bZT.job[6].M = B_;

    // ---- D launch: pretD = (r*gx) @ Wt2, all nodes ----
    GBatch bD = {};
    bD.job[0].seg[0] = mkseg(rgxf, 0, 20, 0);
    bD.job[0].nseg = 1; bD.job[0].C = pretD; bD.job[0].ldc = D_; bD.job[0].mode = 1; bD.job[0].M = N_ * B_;

    // ---- run ----
    wconv_k<<<dim3(40, 40, 21), dim3(32, 8)>>>(W_in, W_out, W_r, W_z, W_t, wth, wtl);
    copy_x_k<<<2048, 256>>>(x, gx, gxf);

    for (int step = 0; step < STEPS_; step++) {
        mma_gemmA<<<dim3(20, 8, 6), 256, SMEM_A_TOTAL>>>(bA);   // edges (128x64 tiles)
        mma_gemm<<<dim3(10, 16, 4), 256, SMEM_TOTAL>>>(bR);     // prer (sparse node jobs)
        cudaEventRecord(evFork, 0);
        cudaStreamWaitEvent(s1, evFork, 0);
        sig_rgx_k<<<2048, 256, 0, s1>>>(prer, gx, rgxf);                 // side stream
        mma_gemm<<<dim3(10, 48, 1), 256, SMEM_TOTAL, s1>>>(bD);          // pretD
        cudaEventRecord(evJoin, s1);
        mma_gemm<<<dim3(10, 16, 7), 256, SMEM_TOTAL>>>(bZT);    // prez + pret (overlaps side)
        cudaStreamWaitEvent(0, evJoin, 0);
        update_k<<<2048, 256>>>(prez, pret, pretD, b_t, gx, gxf);
    }
    transpose_k<<<2048, 256>>>(gx, out);
}

// round 15
// speedup vs baseline: 1.5269x; 1.1245x over previous
#include <cuda_runtime.h>
#include <cuda_bf16.h>
#include <cuda_fp16.h>
#include <cstdint>
#include <math.h>

#define B_ 1024
#define N_ 6
#define D_ 1280
#define STEPS_ 5
#define TOT (B_*N_*D_)
#define BD ((long long)B_*D_)
#define DDLL (1280LL*1280LL)

// ---------------- scratch (static device globals; no allocations) -------------
// All activation buffers are NODE-MAJOR: index (n*B + b)*D + d
__device__ float g_gx [TOT];
__device__ float g_prer[TOT];
__device__ float g_prez[TOT];
__device__ float g_pret[TOT];
__device__ float g_pretD[TOT];
__device__ __half g_gxf [TOT];
__device__ __half g_ainf[TOT];
__device__ __half g_aoutf[TOT];
__device__ __half g_rgxf[TOT];
// 21 transposed weight matrices (1280x1280), fp16 hi/lo (22-bit effective)
__device__ __half g_wth[21u*1280u*1280u];
__device__ __half g_wtl[21u*1280u*1280u];

// ---------------- PTX helpers (stable ISA only) --------------------------------
__device__ __forceinline__ uint32_t smem_u32(const void* p) {
    uint32_t a;
    asm("{ .reg .u64 t; cvta.to.shared.u64 t, %1; cvt.u32.u64 %0, t; }" : "=r"(a) : "l"(p));
    return a;
}
__device__ __forceinline__ void cpa16(uint32_t dst, const void* src) {
    asm volatile("cp.async.cg.shared.global [%0], [%1], 16;" :: "r"(dst), "l"(src));
}
#define CPA_COMMIT() asm volatile("cp.async.commit_group;" ::: "memory")
#define CPA_WAIT1()  asm volatile("cp.async.wait_group 1;" ::: "memory")
#define CPA_WAIT0()  asm volatile("cp.async.wait_group 0;" ::: "memory")

#define LDSM4(r, a) \
    asm volatile("ldmatrix.sync.aligned.m8n8.x4.shared.b16 {%0,%1,%2,%3}, [%4];" \
        : "=r"((r)[0]), "=r"((r)[1]), "=r"((r)[2]), "=r"((r)[3]) : "r"(a))

__device__ __forceinline__ void mma16816(float* c, const uint32_t* a, const uint32_t* b) {
    asm volatile("mma.sync.aligned.m16n8k16.row.col.f32.f16.f16.f32 "
        "{%0,%1,%2,%3}, {%4,%5,%6,%7}, {%8,%9}, {%0,%1,%2,%3};"
        : "+f"(c[0]), "+f"(c[1]), "+f"(c[2]), "+f"(c[3])
        : "r"(a[0]), "r"(a[1]), "r"(a[2]), "r"(a[3]), "r"(b[0]), "r"(b[1]));
}

__device__ __forceinline__ void split2h(float v, __half& h, __half& l) {
    h = __float2half(v);
    l = __float2half(v - __half2float(h));
}

// ---------------- shared job structs --------------------------------------------
struct GSeg {
    const __half* A;
    const __half* Bh; const __half* Bl;   // Bl == nullptr -> single-pass segment
    const float* bias; long long lda;
};
struct GJob {
    GSeg seg[3];
    float* C; __half* Ch;
    long long ldc; int nseg; int mode;    // 0: fp16 out (+bias); 1: fp32 out (+bias)
    int M;
};
struct GBatch { GJob job[8]; };

// ================= kernel 1: 128x64 tiles (A / R / ZT phases) ====================
#define STA_BYTES 32768
#define SMEM_A_TOTAL (2*STA_BYTES)

__global__ void __launch_bounds__(256, 2) mma_gemmA(GBatch batch) {
    extern __shared__ char smem[];
    const GJob& job = batch.job[blockIdx.z];
    const int row0 = blockIdx.y * 128;
    if (row0 >= job.M) return;
    const uint32_t sb = smem_u32(smem);
    const int tid = threadIdx.x;
    const int lane = tid & 31, wid = tid >> 5;
    const int wm = wid & 3, wn = wid >> 2;          // 4x2 warp grid, warp tile 32x32
    const int col0 = blockIdx.x * 64;

    float acc[2][4][4];
#pragma unroll
    for (int mt = 0; mt < 2; mt++)
#pragma unroll
        for (int nt = 0; nt < 4; nt++)
#pragma unroll
            for (int q = 0; q < 4; q++) acc[mt][nt][q] = 0.f;

    const int nchunks = job.nseg * 20;

    auto load_chunk = [&](int c, int s) {
        const int sg = c / 20, kc = c % 20;
        const GSeg& S = job.seg[sg];
        const uint32_t base = sb + s * STA_BYTES;
        const __half* gA  = S.A  + (long long)row0 * S.lda + kc * 64;
        const __half* gBh = S.Bh + (long long)col0 * 1280 + kc * 64;
#pragma unroll
        for (int i = 0; i < 4; i++) {
            int idx = tid + i * 256;
            int r = idx >> 3, c8 = idx & 7;
            uint32_t sw = (uint32_t)(r * 128 + ((c8 ^ (r & 7)) << 4));
            cpa16(base + sw, gA + (long long)r * S.lda + c8 * 8);
        }
#pragma unroll
        for (int i = 0; i < 2; i++) {
            int idx = tid + i * 256;
            int r = idx >> 3, c8 = idx & 7;
            uint32_t sw = (uint32_t)(r * 128 + ((c8 ^ (r & 7)) << 4));
            long long gb = (long long)r * 1280 + c8 * 8;
            cpa16(base + 16384 + sw, gBh + gb);
        }
        if (S.Bl) {
            const __half* gBl = S.Bl + (long long)col0 * 1280 + kc * 64;
#pragma unroll
            for (int i = 0; i < 2; i++) {
                int idx = tid + i * 256;
                int r = idx >> 3, c8 = idx & 7;
                uint32_t sw = (uint32_t)(r * 128 + ((c8 ^ (r & 7)) << 4));
                cpa16(base + 24576 + sw, gBl + (long long)r * 1280 + c8 * 8);
            }
        }
        CPA_COMMIT();
    };

    load_chunk(0, 0);

    const int g = lane >> 3;
    for (int c = 0; c < nchunks; c++) {
        const int s = c & 1;
        if (c + 1 < nchunks) { load_chunk(c + 1, s ^ 1); CPA_WAIT1(); }
        else                 { CPA_WAIT0(); }
        __syncthreads();

        const bool dolo = (job.seg[c / 20].Bl != nullptr);
        const uint32_t AB  = sb + s * STA_BYTES;
        const uint32_t BhB = AB + 16384;
        const uint32_t BlB = AB + 24576;

#pragma unroll
        for (int ks = 0; ks < 4; ks++) {
            uint32_t a[2][4], bh[4][2];
#pragma unroll
            for (int mt = 0; mt < 2; mt++) {
                int ar = wm * 32 + mt * 16 + ((g & 1) << 3) + (lane & 7);
                int ac = ks * 2 + (g >> 1);
                uint32_t off = (uint32_t)(ar * 128 + ((ac ^ (ar & 7)) << 4));
                LDSM4(a[mt], AB + off);
            }
#pragma unroll
            for (int p = 0; p < 2; p++) {
                int br = wn * 32 + p * 16 + ((g >> 1) << 3) + (lane & 7);
                int bc = ks * 2 + (g & 1);
                uint32_t off = (uint32_t)(br * 128 + ((bc ^ (br & 7)) << 4));
                uint32_t t0[4];
                LDSM4(t0, BhB + off);
                bh[2*p][0] = t0[0]; bh[2*p][1] = t0[1];
                bh[2*p+1][0] = t0[2]; bh[2*p+1][1] = t0[3];
            }
#pragma unroll
            for (int mt = 0; mt < 2; mt++)
#pragma unroll
                for (int nt = 0; nt < 4; nt++)
                    mma16816(acc[mt][nt], a[mt], bh[nt]);
            if (dolo) {
                uint32_t bl[4][2];
#pragma unroll
                for (int p = 0; p < 2; p++) {
                    int br = wn * 32 + p * 16 + ((g >> 1) << 3) + (lane & 7);
                    int bc = ks * 2 + (g & 1);
                    uint32_t off = (uint32_t)(br * 128 + ((bc ^ (br & 7)) << 4));
                    uint32_t t1[4];
                    LDSM4(t1, BlB + off);
                    bl[2*p][0] = t1[0]; bl[2*p][1] = t1[1];
                    bl[2*p+1][0] = t1[2]; bl[2*p+1][1] = t1[3];
                }
#pragma unroll
                for (int mt = 0; mt < 2; mt++)
#pragma unroll
                    for (int nt = 0; nt < 4; nt++)
                        mma16816(acc[mt][nt], a[mt], bl[nt]);
            }
        }
        __syncthreads();
    }

    const long long ldc = job.ldc;
    const int rbase = row0 + wm * 32;
    const int cbase = col0 + wn * 32;
#pragma unroll
    for (int nt = 0; nt < 4; nt++) {
        const int col = cbase + nt * 8 + ((lane & 3) << 1);
        float bv0 = 0.f, bv1 = 0.f;
        for (int sg = 0; sg < job.nseg; sg++) {
            const float* bp = job.seg[sg].bias;
            if (bp) { bv0 += bp[col]; bv1 += bp[col + 1]; }
        }
#pragma unroll
        for (int mt = 0; mt < 2; mt++) {
            const int r1 = rbase + mt * 16 + (lane >> 2);
            const int r2 = r1 + 8;
            const float* a4 = acc[mt][nt];
            if (job.mode == 1) {
                *(float2*)&job.C[(long long)r1 * ldc + col] = make_float2(a4[0] + bv0, a4[1] + bv1);
                *(float2*)&job.C[(long long)r2 * ldc + col] = make_float2(a4[2] + bv0, a4[3] + bv1);
            } else {
                *(__half2*)&job.Ch[(long long)r1 * ldc + col] =
                    __halves2half2(__float2half(a4[0] + bv0), __float2half(a4[1] + bv1));
                *(__half2*)&job.Ch[(long long)r2 * ldc + col] =
                    __halves2half2(__float2half(a4[2] + bv0), __float2half(a4[3] + bv1));
            }
        }
    }
}

// ================= kernel 2: 128x128 tiles (phase D — large M, 2-pass) ==========
#define ST_BYTES 49152
#define SMEM_TOTAL (2*ST_BYTES)

__global__ void __launch_bounds__(256, 2) mma_gemm(GBatch batch) {
    extern __shared__ char smem[];
    const GJob& job = batch.job[blockIdx.z];
    const int row0 = blockIdx.y * 128;
    if (row0 >= job.M) return;
    const uint32_t sb = smem_u32(smem);
    const int tid = threadIdx.x;
    const int lane = tid & 31, wid = tid >> 5;
    const int wm = wid & 1, wn = wid >> 1;          // 2x4 warp grid, warp tile 64x32
    const int col0 = blockIdx.x * 128;

    float acc[4][4][4];
#pragma unroll
    for (int mt = 0; mt < 4; mt++)
#pragma unroll
        for (int nt = 0; nt < 4; nt++)
#pragma unroll
            for (int q = 0; q < 4; q++) acc[mt][nt][q] = 0.f;

    const int nchunks = job.nseg * 20;

    auto load_chunk = [&](int c, int s) {
        const int sg = c / 20, kc = c % 20;
        const GSeg& S = job.seg[sg];
        const uint32_t base = sb + s * ST_BYTES;
        const __half* gA  = S.A  + (long long)row0 * S.lda + kc * 64;
        const __half* gBh = S.Bh + (long long)col0 * 1280 + kc * 64;
        const __half* gBl = S.Bl + (long long)col0 * 1280 + kc * 64;
#pragma unroll
        for (int i = 0; i < 4; i++) {
            int idx = tid + i * 256;
            int r = idx >> 3, c8 = idx & 7;
            uint32_t sw = (uint32_t)(r * 128 + ((c8 ^ (r & 7)) << 4));
            cpa16(base + sw, gA + (long long)r * S.lda + c8 * 8);
        }
#pragma unroll
        for (int i = 0; i < 4; i++) {
            int idx = tid + i * 256;
            int r = idx >> 3, c8 = idx & 7;
            uint32_t sw = (uint32_t)(r * 128 + ((c8 ^ (r & 7)) << 4));
            long long gb = (long long)r * 1280 + c8 * 8;
            cpa16(base + 16384 + sw, gBh + gb);
            cpa16(base + 32768 + sw, gBl + gb);
        }
        CPA_COMMIT();
    };

    load_chunk(0, 0);

    const int g = lane >> 3;
    for (int c = 0; c < nchunks; c++) {
        const int s = c & 1;
        if (c + 1 < nchunks) { load_chunk(c + 1, s ^ 1); CPA_WAIT1(); }
        else                 { CPA_WAIT0(); }
        __syncthreads();

        const uint32_t AB  = sb + s * ST_BYTES;
        const uint32_t BhB = AB + 16384;
        const uint32_t BlB = AB + 32768;

#pragma unroll
        for (int ks = 0; ks < 4; ks++) {
            uint32_t bh[4][2], bl[4][2];
#pragma unroll
            for (int p = 0; p < 2; p++) {
                int br = wn * 32 + p * 16 + ((g >> 1) << 3) + (lane & 7);
                int bc = ks * 2 + (g & 1);
                uint32_t off = (uint32_t)(br * 128 + ((bc ^ (br & 7)) << 4));
                uint32_t t0[4], t1[4];
                LDSM4(t0, BhB + off);
                bh[2*p][0] = t0[0]; bh[2*p][1] = t0[1];
                bh[2*p+1][0] = t0[2]; bh[2*p+1][1] = t0[3];
                LDSM4(t1, BlB + off);
                bl[2*p][0] = t1[0]; bl[2*p][1] = t1[1];
                bl[2*p+1][0] = t1[2]; bl[2*p+1][1] = t1[3];
            }
#pragma unroll
            for (int mt = 0; mt < 4; mt++) {
                int ar = wm * 64 + mt * 16 + ((g & 1) << 3) + (lane & 7);
                int ac = ks * 2 + (g >> 1);
                uint32_t off = (uint32_t)(ar * 128 + ((ac ^ (ar & 7)) << 4));
                uint32_t a[4];
                LDSM4(a, AB + off);
#pragma unroll
                for (int nt = 0; nt < 4; nt++) {
                    mma16816(acc[mt][nt], a, bh[nt]);
                    mma16816(acc[mt][nt], a, bl[nt]);
                }
            }
        }
        __syncthreads();
    }

    const long long ldc = job.ldc;
    const int rbase = row0 + wm * 64;
    const int cbase = col0 + wn * 32;
#pragma unroll
    for (int nt = 0; nt < 4; nt++) {
        const int col = cbase + nt * 8 + ((lane & 3) << 1);
        float bv0 = 0.f, bv1 = 0.f;
        for (int sg = 0; sg < job.nseg; sg++) {
            const float* bp = job.seg[sg].bias;
            if (bp) { bv0 += bp[col]; bv1 += bp[col + 1]; }
        }
#pragma unroll
        for (int mt = 0; mt < 4; mt++) {
            const int r1 = rbase + mt * 16 + (lane >> 2);
            const int r2 = r1 + 8;
            const float* a4 = acc[mt][nt];
            if (job.mode == 1) {
                *(float2*)&job.C[(long long)r1 * ldc + col] = make_float2(a4[0] + bv0, a4[1] + bv1);
                *(float2*)&job.C[(long long)r2 * ldc + col] = make_float2(a4[2] + bv0, a4[3] + bv1);
            } else {
                *(__half2*)&job.Ch[(long long)r1 * ldc + col] =
                    __halves2half2(__float2half(a4[0] + bv0), __float2half(a4[1] + bv1));
                *(__half2*)&job.Ch[(long long)r2 * ldc + col] =
                    __halves2half2(__float2half(a4[2] + bv0), __float2half(a4[3] + bv1));
            }
        }
    }
}

// ---------------- weight transpose + fp16 split (once per call) -----------------
__global__ void wconv_k(const float* __restrict__ Win, const float* __restrict__ Wout,
                        const float* __restrict__ Wr, const float* __restrict__ Wz,
                        const float* __restrict__ Wt,
                        __half* __restrict__ wth, __half* __restrict__ wtl) {
    __shared__ float tile[32][33];
    const int slot = blockIdx.z;
    const int f0 = blockIdx.x * 32, d0 = blockIdx.y * 32;
    const float* base;
    if (slot < 6)       base = Win  + (long long)slot * DDLL;
    else if (slot < 12) base = Wout + (long long)(slot - 6) * DDLL;
    else {
        int gq = (slot - 12) / 3, q = (slot - 12) % 3;
        base = (gq == 0 ? Wr : (gq == 1 ? Wz : Wt)) + (long long)q * DDLL;
    }
    for (int i = threadIdx.y; i < 32; i += 8)
        tile[i][threadIdx.x] = base[(long long)(d0 + i) * 1280 + f0 + threadIdx.x];
    __syncthreads();
    __half* oh = wth + (long long)slot * DDLL;
    __half* ol = wtl + (long long)slot * DDLL;
    for (int i = threadIdx.y; i < 32; i += 8) {
        float v = tile[threadIdx.x][i];
        __half h, l; split2h(v, h, l);
        oh[(long long)(f0 + i) * 1280 + d0 + threadIdx.x] = h;
        ol[(long long)(f0 + i) * 1280 + d0 + threadIdx.x] = l;
    }
}

// ---------------- elementwise kernels (node-major) ------------------------------
__global__ void copy_x_k(const float* __restrict__ x, float* __restrict__ gx,
                         __half* __restrict__ gf) {
    for (long long j = blockIdx.x * blockDim.x + threadIdx.x; j < TOT;
         j += (long long)gridDim.x * blockDim.x) {
        int n = (int)(j / BD);
        long long rem = j - (long long)n * BD;
        int b = (int)(rem / D_), d = (int)(rem % D_);
        float v = x[((long long)b * N_ + n) * D_ + d];
        gx[j] = v;
        gf[j] = __float2half(v);
    }
}

__global__ void sig_rgx_k(const float* __restrict__ prer, const float* __restrict__ gx,
                          __half* __restrict__ rf) {
    for (int i = blockIdx.x * blockDim.x + threadIdx.x; i < TOT; i += gridDim.x * blockDim.x) {
        float r = 1.f / (1.f + expf(-prer[i]));
        rf[i] = __float2half(r * gx[i]);
    }
}

__global__ void update_k(const float* __restrict__ prez, const float* __restrict__ pret,
                         const float* __restrict__ pretD, const float* __restrict__ b_t,
                         float* __restrict__ gx, __half* __restrict__ gf) {
    const long long lim = 4LL * BD;
    for (long long i = blockIdx.x * blockDim.x + threadIdx.x; i < TOT;
         i += (long long)gridDim.x * blockDim.x) {
        float pt = (i < lim) ? pret[i] : b_t[(int)(i % D_)];
        float z = 1.f / (1.f + expf(-prez[i]));
        float h = tanhf(pt + pretD[i]);
        float gv = gx[i];
        float ng = gv + z * (h - gv);
        gx[i] = ng;
        gf[i] = __float2half(ng);
    }
}

__global__ void transpose_k(const float* __restrict__ gx, float* __restrict__ out) {
    for (long long idx = blockIdx.x * blockDim.x + threadIdx.x; idx < TOT;
         idx += (long long)gridDim.x * blockDim.x) {
        int b = (int)(idx / ((long long)N_ * D_));
        long long r = idx - (long long)b * N_ * D_;
        int d = (int)(r / N_), n = (int)(r % N_);
        out[idx] = gx[((long long)n * B_ + b) * D_ + d];
    }
}

// ---------------- host orchestration ------------------------------------------
extern "C" void kernel_launch(void* const* d_in, const int* in_sizes, int n_in,
                              void* d_out, int out_size) {
    const float* x     = (const float*)d_in[0];
    const float* W_in  = (const float*)d_in[2];
    const float* b_in  = (const float*)d_in[3];
    const float* W_out = (const float*)d_in[4];
    const float* b_out = (const float*)d_in[5];
    const float* W_r   = (const float*)d_in[6];
    const float* b_r   = (const float*)d_in[7];
    const float* W_z   = (const float*)d_in[8];
    const float* b_z   = (const float*)d_in[9];
    const float* W_t   = (const float*)d_in[10];
    const float* b_t   = (const float*)d_in[11];
    float* out = (float*)d_out;

    float *gx, *prer, *prez, *pret, *pretD;
    __half *gxf, *ainf, *aoutf, *rgxf, *wth, *wtl;
    cudaGetSymbolAddress((void**)&gx,    g_gx);
    cudaGetSymbolAddress((void**)&prer,  g_prer);
    cudaGetSymbolAddress((void**)&prez,  g_prez);
    cudaGetSymbolAddress((void**)&pret,  g_pret);
    cudaGetSymbolAddress((void**)&pretD, g_pretD);
    cudaGetSymbolAddress((void**)&gxf,   g_gxf);
    cudaGetSymbolAddress((void**)&ainf,  g_ainf);
    cudaGetSymbolAddress((void**)&aoutf, g_aoutf);
    cudaGetSymbolAddress((void**)&rgxf,  g_rgxf);
    cudaGetSymbolAddress((void**)&wth,   g_wth);
    cudaGetSymbolAddress((void**)&wtl,   g_wtl);

    cudaFuncSetAttribute(mma_gemm,  cudaFuncAttributeMaxDynamicSharedMemorySize, SMEM_TOTAL);
    cudaFuncSetAttribute(mma_gemmA, cudaFuncAttributeMaxDynamicSharedMemorySize, SMEM_A_TOTAL);

    static cudaStream_t s1 = nullptr;
    static cudaEvent_t evFork = nullptr, evJoin = nullptr;
    if (!s1) {
        cudaStreamCreateWithFlags(&s1, cudaStreamNonBlocking);
        cudaEventCreateWithFlags(&evFork, cudaEventDisableTiming);
        cudaEventCreateWithFlags(&evJoin, cudaEventDisableTiming);
    }

    auto wslot = [&](int s) { return (long long)s * DDLL; };

    // ---- Phase A (mode 0): edge propagation, node-major, 2-pass ----
    GBatch bA = {};
    {
        auto seg_in = [&](int src, int et) {
            GSeg s{};
            s.A = gxf + (long long)src * BD; s.lda = D_;
            s.Bh = wth + wslot(et); s.Bl = wtl + wslot(et);
            s.bias = b_in + (long long)et * D_;
            return s;
        };
        auto seg_out = [&](int tgt, int et) {
            GSeg s{};
            s.A = gxf + (long long)tgt * BD; s.lda = D_;
            s.Bh = wth + wslot(6 + et); s.Bl = wtl + wslot(6 + et);
            s.bias = b_out + (long long)et * D_;
            return s;
        };
        auto setC = [&](GJob& j, __half* cf, int node) {
            j.Ch = cf + (long long)node * BD;
            j.ldc = D_; j.mode = 0; j.M = B_;
        };
        bA.job[0].seg[0] = seg_in(0, 2); bA.job[0].seg[1] = seg_in(1, 4); bA.job[0].seg[2] = seg_in(2, 5);
        bA.job[0].nseg = 3; setC(bA.job[0], ainf, 3);
        bA.job[1].seg[0] = seg_out(1, 0); bA.job[1].seg[1] = seg_out(2, 1); bA.job[1].seg[2] = seg_out(3, 2);
        bA.job[1].nseg = 3; setC(bA.job[1], aoutf, 0);
        bA.job[2].seg[0] = seg_in(0, 1); bA.job[2].seg[1] = seg_in(1, 3);
        bA.job[2].nseg = 2; setC(bA.job[2], ainf, 2);
        bA.job[3].seg[0] = seg_out(2, 3); bA.job[3].seg[1] = seg_out(3, 4);
        bA.job[3].nseg = 2; setC(bA.job[3], aoutf, 1);
        bA.job[4].seg[0] = seg_in(0, 0); bA.job[4].nseg = 1; setC(bA.job[4], ainf, 1);
        bA.job[5].seg[0] = seg_out(3, 5); bA.job[5].nseg = 1; setC(bA.job[5], aoutf, 2);
    }

    // seg maker: lo=true -> 2-pass; lo=false -> single-pass (r/z gates)
    auto mkseg = [&](const __half* A, int node, int gslot, const float* bias, bool lo) {
        GSeg s{};
        s.A = A + (long long)node * BD; s.lda = D_;
        s.Bh = wth + wslot(gslot); s.Bl = lo ? (wtl + wslot(gslot)) : nullptr;
        s.bias = bias;
        return s;
    };

    // ---- R launch: prer by node group (1-pass, sigmoid-damped) ----
    GBatch bR = {};
    bR.job[0].seg[0] = mkseg(ainf, 1, 12, b_r, false);
    bR.job[0].seg[1] = mkseg(aoutf, 1, 13, 0, false);
    bR.job[0].seg[2] = mkseg(gxf, 1, 14, 0, false);
    bR.job[0].nseg = 3; bR.job[0].C = prer + BD; bR.job[0].ldc = D_; bR.job[0].mode = 1; bR.job[0].M = 2 * B_;
    bR.job[1].seg[0] = mkseg(gxf, 4, 14, b_r, false);
    bR.job[1].nseg = 1; bR.job[1].C = prer + 4 * BD; bR.job[1].ldc = D_; bR.job[1].mode = 1; bR.job[1].M = 2 * B_;
    bR.job[2].seg[0] = mkseg(aoutf, 0, 13, b_r, false);
    bR.job[2].seg[1] = mkseg(gxf, 0, 14, 0, false);
    bR.job[2].nseg = 2; bR.job[2].C = prer; bR.job[2].ldc = D_; bR.job[2].mode = 1; bR.job[2].M = B_;
    bR.job[3].seg[0] = mkseg(ainf, 3, 12, b_r, false);
    bR.job[3].seg[1] = mkseg(gxf, 3, 14, 0, false);
    bR.job[3].nseg = 2; bR.job[3].C = prer + 3 * BD; bR.job[3].ldc = D_; bR.job[3].mode = 1; bR.job[3].M = B_;

    // ---- ZT launch: prez (1-pass) + pret partial (2-pass) ----
    GBatch bZT = {};
    bZT.job[0].seg[0] = mkseg(ainf, 1, 15, b_z, false);
    bZT.job[0].seg[1] = mkseg(aoutf, 1, 16, 0, false);
    bZT.job[0].seg[2] = mkseg(gxf, 1, 17, 0, false);
    bZT.job[0].nseg = 3; bZT.job[0].C = prez + BD; bZT.job[0].ldc = D_; bZT.job[0].mode = 1; bZT.job[0].M = 2 * B_;
    bZT.job[1].seg[0] = mkseg(gxf, 4, 17, b_z, false);
    bZT.job[1].nseg = 1; bZT.job[1].C = prez + 4 * BD; bZT.job[1].ldc = D_; bZT.job[1].mode = 1; bZT.job[1].M = 2 * B_;
    bZT.job[2].seg[0] = mkseg(ainf, 1, 18, b_t, true);
    bZT.job[2].seg[1] = mkseg(aoutf, 1, 19, 0, true);
    bZT.job[2].nseg = 2; bZT.job[2].C = pret + BD; bZT.job[2].ldc = D_; bZT.job[2].mode = 1; bZT.job[2].M = 2 * B_;
    bZT.job[3].seg[0] = mkseg(aoutf, 0, 16, b_z, false);
    bZT.job[3].seg[1] = mkseg(gxf, 0, 17, 0, false);
    bZT.job[3].nseg = 2; bZT.job[3].C = prez; bZT.job[3].ldc = D_; bZT.job[3].mode = 1; bZT.job[3].M = B_;
    bZT.job[4].seg[0] = mkseg(ainf, 3, 15, b_z, false);
    bZT.job[4].seg[1] = mkseg(gxf, 3, 17, 0, false);
    bZT.job[4].nseg = 2; bZT.job[4].C = prez + 3 * BD; bZT.job[4].ldc = D_; bZT.job[4].mode = 1; bZT.job[4].M = B_;
    bZT.job[5].seg[0] = mkseg(aoutf, 0, 19, b_t, true);
    bZT.job[5].nseg = 1; bZT.job[5].C = pret; bZT.job[5].ldc = D_; bZT.job[5].mode = 1; bZT.job[5].M = B_;
    bZT.job[6].seg[0] = mkseg(ainf, 3, 18, b_t, true);
    bZT.job[6].nseg = 1; bZT.job[6].C = pret + 3 * BD; bZT.job[6].ldc = D_; bZT.job[6].mode = 1; bZT.job[6].M = B_;

    // ---- D launch: pretD = (r*gx) @ Wt2, all nodes, 2-pass (hidden on side) ----
    GBatch bD = {};
    {
        GSeg s{};
        s.A = rgxf; s.lda = D_;
        s.Bh = wth + wslot(20); s.Bl = wtl + wslot(20); s.bias = 0;
        bD.job[0].seg[0] = s; bD.job[0].nseg = 1;
        bD.job[0].C = pretD; bD.job[0].ldc = D_; bD.job[0].mode = 1; bD.job[0].M = N_ * B_;
    }

    // ---- run ----
    wconv_k<<<dim3(40, 40, 21), dim3(32, 8)>>>(W_in, W_out, W_r, W_z, W_t, wth, wtl);
    copy_x_k<<<2048, 256>>>(x, gx, gxf);

    for (int step = 0; step < STEPS_; step++) {
        mma_gemmA<<<dim3(20, 8, 6),  256, SMEM_A_TOTAL>>>(bA);  // edges (2-pass)
        mma_gemmA<<<dim3(20, 16, 4), 256, SMEM_A_TOTAL>>>(bR);  // prer (1-pass)
        cudaEventRecord(evFork, 0);
        cudaStreamWaitEvent(s1, evFork, 0);
        sig_rgx_k<<<2048, 256, 0, s1>>>(prer, gx, rgxf);                 // side stream
        mma_gemm<<<dim3(10, 48, 1), 256, SMEM_TOTAL, s1>>>(bD);          // pretD (2-pass)
        cudaEventRecord(evJoin, s1);
        mma_gemmA<<<dim3(20, 16, 7), 256, SMEM_A_TOTAL>>>(bZT); // prez(1p) + pret(2p)
        cudaStreamWaitEvent(0, evJoin, 0);
        update_k<<<2048, 256>>>(prez, pret, pretD, b_t, gx, gxf);
    }
    transpose_k<<<2048, 256>>>(gx, out);
}

// round 16
// speedup vs baseline: 1.6122x; 1.0559x over previous
#include <cuda_runtime.h>
#include <cuda_bf16.h>
#include <cuda_fp16.h>
#include <cstdint>
#include <math.h>

#define B_ 1024
#define N_ 6
#define D_ 1280
#define STEPS_ 5
#define TOT (B_*N_*D_)
#define BD ((long long)B_*D_)
#define DDLL (1280LL*1280LL)

// ---------------- scratch (static device globals; no allocations) -------------
// All activation buffers are NODE-MAJOR: index (n*B + b)*D + d
__device__ float g_gx [TOT];
__device__ float g_prer[TOT];
__device__ float g_prez[TOT];
__device__ float g_pret[TOT];
__device__ float g_pretD[TOT];
__device__ __half g_gxf [TOT];
__device__ __half g_ainf[TOT];
__device__ __half g_aoutf[TOT];
__device__ __half g_rgxf[TOT];
// 21 transposed weight matrices (1280x1280), fp16 hi/lo (22-bit effective)
__device__ __half g_wth[21u*1280u*1280u];
__device__ __half g_wtl[21u*1280u*1280u];

// ---------------- PTX helpers (stable ISA only) --------------------------------
__device__ __forceinline__ uint32_t smem_u32(const void* p) {
    uint32_t a;
    asm("{ .reg .u64 t; cvta.to.shared.u64 t, %1; cvt.u32.u64 %0, t; }" : "=r"(a) : "l"(p));
    return a;
}
__device__ __forceinline__ void cpa16(uint32_t dst, const void* src) {
    asm volatile("cp.async.cg.shared.global [%0], [%1], 16;" :: "r"(dst), "l"(src));
}
#define CPA_COMMIT() asm volatile("cp.async.commit_group;" ::: "memory")
#define CPA_WAIT1()  asm volatile("cp.async.wait_group 1;" ::: "memory")
#define CPA_WAIT0()  asm volatile("cp.async.wait_group 0;" ::: "memory")

#define LDSM4(r, a) \
    asm volatile("ldmatrix.sync.aligned.m8n8.x4.shared.b16 {%0,%1,%2,%3}, [%4];" \
        : "=r"((r)[0]), "=r"((r)[1]), "=r"((r)[2]), "=r"((r)[3]) : "r"(a))

__device__ __forceinline__ void mma16816(float* c, const uint32_t* a, const uint32_t* b) {
    asm volatile("mma.sync.aligned.m16n8k16.row.col.f32.f16.f16.f32 "
        "{%0,%1,%2,%3}, {%4,%5,%6,%7}, {%8,%9}, {%0,%1,%2,%3};"
        : "+f"(c[0]), "+f"(c[1]), "+f"(c[2]), "+f"(c[3])
        : "r"(a[0]), "r"(a[1]), "r"(a[2]), "r"(a[3]), "r"(b[0]), "r"(b[1]));
}

__device__ __forceinline__ void split2h(float v, __half& h, __half& l) {
    h = __float2half(v);
    l = __float2half(v - __half2float(h));
}

// ---------------- shared job structs --------------------------------------------
struct GSeg {
    const __half* A;
    const __half* Bh; const __half* Bl;   // Bl == nullptr -> single-pass segment
    const float* bias; long long lda;
};
struct GJob {
    GSeg seg[3];
    float* C; __half* Ch;
    long long ldc; int nseg; int mode;    // 0: fp16 out (+bias); 1: fp32 out (+bias)
    int M;
};
struct GBatch { GJob job[8]; };

// ================= kernel 1: 128x64 tiles, 2-pass-capable (A / T phases) ========
#define STA_BYTES 32768
#define SMEM_A_TOTAL (2*STA_BYTES)

__global__ void __launch_bounds__(256, 2) mma_gemmA(GBatch batch) {
    extern __shared__ char smem[];
    const GJob& job = batch.job[blockIdx.z];
    const int row0 = blockIdx.y * 128;
    if (row0 >= job.M) return;
    const uint32_t sb = smem_u32(smem);
    const int tid = threadIdx.x;
    const int lane = tid & 31, wid = tid >> 5;
    const int wm = wid & 3, wn = wid >> 2;          // 4x2 warp grid, warp tile 32x32
    const int col0 = blockIdx.x * 64;

    float acc[2][4][4];
#pragma unroll
    for (int mt = 0; mt < 2; mt++)
#pragma unroll
        for (int nt = 0; nt < 4; nt++)
#pragma unroll
            for (int q = 0; q < 4; q++) acc[mt][nt][q] = 0.f;

    const int nchunks = job.nseg * 20;

    auto load_chunk = [&](int c, int s) {
        const int sg = c / 20, kc = c % 20;
        const GSeg& S = job.seg[sg];
        const uint32_t base = sb + s * STA_BYTES;
        const __half* gA  = S.A  + (long long)row0 * S.lda + kc * 64;
        const __half* gBh = S.Bh + (long long)col0 * 1280 + kc * 64;
#pragma unroll
        for (int i = 0; i < 4; i++) {
            int idx = tid + i * 256;
            int r = idx >> 3, c8 = idx & 7;
            uint32_t sw = (uint32_t)(r * 128 + ((c8 ^ (r & 7)) << 4));
            cpa16(base + sw, gA + (long long)r * S.lda + c8 * 8);
        }
#pragma unroll
        for (int i = 0; i < 2; i++) {
            int idx = tid + i * 256;
            int r = idx >> 3, c8 = idx & 7;
            uint32_t sw = (uint32_t)(r * 128 + ((c8 ^ (r & 7)) << 4));
            long long gb = (long long)r * 1280 + c8 * 8;
            cpa16(base + 16384 + sw, gBh + gb);
        }
        if (S.Bl) {
            const __half* gBl = S.Bl + (long long)col0 * 1280 + kc * 64;
#pragma unroll
            for (int i = 0; i < 2; i++) {
                int idx = tid + i * 256;
                int r = idx >> 3, c8 = idx & 7;
                uint32_t sw = (uint32_t)(r * 128 + ((c8 ^ (r & 7)) << 4));
                cpa16(base + 24576 + sw, gBl + (long long)r * 1280 + c8 * 8);
            }
        }
        CPA_COMMIT();
    };

    load_chunk(0, 0);

    const int g = lane >> 3;
    for (int c = 0; c < nchunks; c++) {
        const int s = c & 1;
        if (c + 1 < nchunks) { load_chunk(c + 1, s ^ 1); CPA_WAIT1(); }
        else                 { CPA_WAIT0(); }
        __syncthreads();

        const bool dolo = (job.seg[c / 20].Bl != nullptr);
        const uint32_t AB  = sb + s * STA_BYTES;
        const uint32_t BhB = AB + 16384;
        const uint32_t BlB = AB + 24576;

#pragma unroll
        for (int ks = 0; ks < 4; ks++) {
            uint32_t a[2][4], bh[4][2];
#pragma unroll
            for (int mt = 0; mt < 2; mt++) {
                int ar = wm * 32 + mt * 16 + ((g & 1) << 3) + (lane & 7);
                int ac = ks * 2 + (g >> 1);
                uint32_t off = (uint32_t)(ar * 128 + ((ac ^ (ar & 7)) << 4));
                LDSM4(a[mt], AB + off);
            }
#pragma unroll
            for (int p = 0; p < 2; p++) {
                int br = wn * 32 + p * 16 + ((g >> 1) << 3) + (lane & 7);
                int bc = ks * 2 + (g & 1);
                uint32_t off = (uint32_t)(br * 128 + ((bc ^ (br & 7)) << 4));
                uint32_t t0[4];
                LDSM4(t0, BhB + off);
                bh[2*p][0] = t0[0]; bh[2*p][1] = t0[1];
                bh[2*p+1][0] = t0[2]; bh[2*p+1][1] = t0[3];
            }
#pragma unroll
            for (int mt = 0; mt < 2; mt++)
#pragma unroll
                for (int nt = 0; nt < 4; nt++)
                    mma16816(acc[mt][nt], a[mt], bh[nt]);
            if (dolo) {
                uint32_t bl[4][2];
#pragma unroll
                for (int p = 0; p < 2; p++) {
                    int br = wn * 32 + p * 16 + ((g >> 1) << 3) + (lane & 7);
                    int bc = ks * 2 + (g & 1);
                    uint32_t off = (uint32_t)(br * 128 + ((bc ^ (br & 7)) << 4));
                    uint32_t t1[4];
                    LDSM4(t1, BlB + off);
                    bl[2*p][0] = t1[0]; bl[2*p][1] = t1[1];
                    bl[2*p+1][0] = t1[2]; bl[2*p+1][1] = t1[3];
                }
#pragma unroll
                for (int mt = 0; mt < 2; mt++)
#pragma unroll
                    for (int nt = 0; nt < 4; nt++)
                        mma16816(acc[mt][nt], a[mt], bl[nt]);
            }
        }
        __syncthreads();
    }

    const long long ldc = job.ldc;
    const int rbase = row0 + wm * 32;
    const int cbase = col0 + wn * 32;
#pragma unroll
    for (int nt = 0; nt < 4; nt++) {
        const int col = cbase + nt * 8 + ((lane & 3) << 1);
        float bv0 = 0.f, bv1 = 0.f;
        for (int sg = 0; sg < job.nseg; sg++) {
            const float* bp = job.seg[sg].bias;
            if (bp) { bv0 += bp[col]; bv1 += bp[col + 1]; }
        }
#pragma unroll
        for (int mt = 0; mt < 2; mt++) {
            const int r1 = rbase + mt * 16 + (lane >> 2);
            const int r2 = r1 + 8;
            const float* a4 = acc[mt][nt];
            if (job.mode == 1) {
                *(float2*)&job.C[(long long)r1 * ldc + col] = make_float2(a4[0] + bv0, a4[1] + bv1);
                *(float2*)&job.C[(long long)r2 * ldc + col] = make_float2(a4[2] + bv0, a4[3] + bv1);
            } else {
                *(__half2*)&job.Ch[(long long)r1 * ldc + col] =
                    __halves2half2(__float2half(a4[0] + bv0), __float2half(a4[1] + bv1));
                *(__half2*)&job.Ch[(long long)r2 * ldc + col] =
                    __halves2half2(__float2half(a4[2] + bv0), __float2half(a4[3] + bv1));
            }
        }
    }
}

// ================= kernel 2: 128x128 tiles, 2-pass (phase D) ====================
#define ST_BYTES 49152
#define SMEM_TOTAL (2*ST_BYTES)

__global__ void __launch_bounds__(256, 2) mma_gemm(GBatch batch) {
    extern __shared__ char smem[];
    const GJob& job = batch.job[blockIdx.z];
    const int row0 = blockIdx.y * 128;
    if (row0 >= job.M) return;
    const uint32_t sb = smem_u32(smem);
    const int tid = threadIdx.x;
    const int lane = tid & 31, wid = tid >> 5;
    const int wm = wid & 1, wn = wid >> 1;          // 2x4 warp grid, warp tile 64x32
    const int col0 = blockIdx.x * 128;

    float acc[4][4][4];
#pragma unroll
    for (int mt = 0; mt < 4; mt++)
#pragma unroll
        for (int nt = 0; nt < 4; nt++)
#pragma unroll
            for (int q = 0; q < 4; q++) acc[mt][nt][q] = 0.f;

    const int nchunks = job.nseg * 20;

    auto load_chunk = [&](int c, int s) {
        const int sg = c / 20, kc = c % 20;
        const GSeg& S = job.seg[sg];
        const uint32_t base = sb + s * ST_BYTES;
        const __half* gA  = S.A  + (long long)row0 * S.lda + kc * 64;
        const __half* gBh = S.Bh + (long long)col0 * 1280 + kc * 64;
        const __half* gBl = S.Bl + (long long)col0 * 1280 + kc * 64;
#pragma unroll
        for (int i = 0; i < 4; i++) {
            int idx = tid + i * 256;
            int r = idx >> 3, c8 = idx & 7;
            uint32_t sw = (uint32_t)(r * 128 + ((c8 ^ (r & 7)) << 4));
            cpa16(base + sw, gA + (long long)r * S.lda + c8 * 8);
        }
#pragma unroll
        for (int i = 0; i < 4; i++) {
            int idx = tid + i * 256;
            int r = idx >> 3, c8 = idx & 7;
            uint32_t sw = (uint32_t)(r * 128 + ((c8 ^ (r & 7)) << 4));
            long long gb = (long long)r * 1280 + c8 * 8;
            cpa16(base + 16384 + sw, gBh + gb);
            cpa16(base + 32768 + sw, gBl + gb);
        }
        CPA_COMMIT();
    };

    load_chunk(0, 0);

    const int g = lane >> 3;
    for (int c = 0; c < nchunks; c++) {
        const int s = c & 1;
        if (c + 1 < nchunks) { load_chunk(c + 1, s ^ 1); CPA_WAIT1(); }
        else                 { CPA_WAIT0(); }
        __syncthreads();

        const uint32_t AB  = sb + s * ST_BYTES;
        const uint32_t BhB = AB + 16384;
        const uint32_t BlB = AB + 32768;

#pragma unroll
        for (int ks = 0; ks < 4; ks++) {
            uint32_t bh[4][2], bl[4][2];
#pragma unroll
            for (int p = 0; p < 2; p++) {
                int br = wn * 32 + p * 16 + ((g >> 1) << 3) + (lane & 7);
                int bc = ks * 2 + (g & 1);
                uint32_t off = (uint32_t)(br * 128 + ((bc ^ (br & 7)) << 4));
                uint32_t t0[4], t1[4];
                LDSM4(t0, BhB + off);
                bh[2*p][0] = t0[0]; bh[2*p][1] = t0[1];
                bh[2*p+1][0] = t0[2]; bh[2*p+1][1] = t0[3];
                LDSM4(t1, BlB + off);
                bl[2*p][0] = t1[0]; bl[2*p][1] = t1[1];
                bl[2*p+1][0] = t1[2]; bl[2*p+1][1] = t1[3];
            }
#pragma unroll
            for (int mt = 0; mt < 4; mt++) {
                int ar = wm * 64 + mt * 16 + ((g & 1) << 3) + (lane & 7);
                int ac = ks * 2 + (g >> 1);
                uint32_t off = (uint32_t)(ar * 128 + ((ac ^ (ar & 7)) << 4));
                uint32_t a[4];
                LDSM4(a, AB + off);
#pragma unroll
                for (int nt = 0; nt < 4; nt++) {
                    mma16816(acc[mt][nt], a, bh[nt]);
                    mma16816(acc[mt][nt], a, bl[nt]);
                }
            }
        }
        __syncthreads();
    }

    const long long ldc = job.ldc;
    const int rbase = row0 + wm * 64;
    const int cbase = col0 + wn * 32;
#pragma unroll
    for (int nt = 0; nt < 4; nt++) {
        const int col = cbase + nt * 8 + ((lane & 3) << 1);
        float bv0 = 0.f, bv1 = 0.f;
        for (int sg = 0; sg < job.nseg; sg++) {
            const float* bp = job.seg[sg].bias;
            if (bp) { bv0 += bp[col]; bv1 += bp[col + 1]; }
        }
#pragma unroll
        for (int mt = 0; mt < 4; mt++) {
            const int r1 = rbase + mt * 16 + (lane >> 2);
            const int r2 = r1 + 8;
            const float* a4 = acc[mt][nt];
            if (job.mode == 1) {
                *(float2*)&job.C[(long long)r1 * ldc + col] = make_float2(a4[0] + bv0, a4[1] + bv1);
                *(float2*)&job.C[(long long)r2 * ldc + col] = make_float2(a4[2] + bv0, a4[3] + bv1);
            } else {
                *(__half2*)&job.Ch[(long long)r1 * ldc + col] =
                    __halves2half2(__float2half(a4[0] + bv0), __float2half(a4[1] + bv1));
                *(__half2*)&job.Ch[(long long)r2 * ldc + col] =
                    __halves2half2(__float2half(a4[2] + bv0), __float2half(a4[3] + bv1));
            }
        }
    }
}

// ================= kernel 3: 128x128 tiles, 1-pass only (R / Z phases) ==========
// No bl buffers: stage = A 16K + Bh 16K = 32K; regs ~100; 2 CTAs/SM.
#define ST1_BYTES 32768
#define SMEM_1P_TOTAL (2*ST1_BYTES)

__global__ void __launch_bounds__(256, 2) mma_gemm1p(GBatch batch) {
    extern __shared__ char smem[];
    const GJob& job = batch.job[blockIdx.z];
    const int row0 = blockIdx.y * 128;
    if (row0 >= job.M) return;
    const uint32_t sb = smem_u32(smem);
    const int tid = threadIdx.x;
    const int lane = tid & 31, wid = tid >> 5;
    const int wm = wid & 1, wn = wid >> 1;          // 2x4 warp grid, warp tile 64x32
    const int col0 = blockIdx.x * 128;

    float acc[4][4][4];
#pragma unroll
    for (int mt = 0; mt < 4; mt++)
#pragma unroll
        for (int nt = 0; nt < 4; nt++)
#pragma unroll
            for (int q = 0; q < 4; q++) acc[mt][nt][q] = 0.f;

    const int nchunks = job.nseg * 20;

    auto load_chunk = [&](int c, int s) {
        const int sg = c / 20, kc = c % 20;
        const GSeg& S = job.seg[sg];
        const uint32_t base = sb + s * ST1_BYTES;
        const __half* gA  = S.A  + (long long)row0 * S.lda + kc * 64;
        const __half* gBh = S.Bh + (long long)col0 * 1280 + kc * 64;
#pragma unroll
        for (int i = 0; i < 4; i++) {
            int idx = tid + i * 256;
            int r = idx >> 3, c8 = idx & 7;
            uint32_t sw = (uint32_t)(r * 128 + ((c8 ^ (r & 7)) << 4));
            cpa16(base + sw, gA + (long long)r * S.lda + c8 * 8);
        }
#pragma unroll
        for (int i = 0; i < 4; i++) {
            int idx = tid + i * 256;
            int r = idx >> 3, c8 = idx & 7;
            uint32_t sw = (uint32_t)(r * 128 + ((c8 ^ (r & 7)) << 4));
            cpa16(base + 16384 + sw, gBh + (long long)r * 1280 + c8 * 8);
        }
        CPA_COMMIT();
    };

    load_chunk(0, 0);

    const int g = lane >> 3;
    for (int c = 0; c < nchunks; c++) {
        const int s = c & 1;
        if (c + 1 < nchunks) { load_chunk(c + 1, s ^ 1); CPA_WAIT1(); }
        else                 { CPA_WAIT0(); }
        __syncthreads();

        const uint32_t AB  = sb + s * ST1_BYTES;
        const uint32_t BhB = AB + 16384;

#pragma unroll
        for (int ks = 0; ks < 4; ks++) {
            uint32_t bh[4][2];
#pragma unroll
            for (int p = 0; p < 2; p++) {
                int br = wn * 32 + p * 16 + ((g >> 1) << 3) + (lane & 7);
                int bc = ks * 2 + (g & 1);
                uint32_t off = (uint32_t)(br * 128 + ((bc ^ (br & 7)) << 4));
                uint32_t t0[4];
                LDSM4(t0, BhB + off);
                bh[2*p][0] = t0[0]; bh[2*p][1] = t0[1];
                bh[2*p+1][0] = t0[2]; bh[2*p+1][1] = t0[3];
            }
#pragma unroll
            for (int mt = 0; mt < 4; mt++) {
                int ar = wm * 64 + mt * 16 + ((g & 1) << 3) + (lane & 7);
                int ac = ks * 2 + (g >> 1);
                uint32_t off = (uint32_t)(ar * 128 + ((ac ^ (ar & 7)) << 4));
                uint32_t a[4];
                LDSM4(a, AB + off);
#pragma unroll
                for (int nt = 0; nt < 4; nt++)
                    mma16816(acc[mt][nt], a, bh[nt]);
            }
        }
        __syncthreads();
    }

    const long long ldc = job.ldc;
    const int rbase = row0 + wm * 64;
    const int cbase = col0 + wn * 32;
#pragma unroll
    for (int nt = 0; nt < 4; nt++) {
        const int col = cbase + nt * 8 + ((lane & 3) << 1);
        float bv0 = 0.f, bv1 = 0.f;
        for (int sg = 0; sg < job.nseg; sg++) {
            const float* bp = job.seg[sg].bias;
            if (bp) { bv0 += bp[col]; bv1 += bp[col + 1]; }
        }
#pragma unroll
        for (int mt = 0; mt < 4; mt++) {
            const int r1 = rbase + mt * 16 + (lane >> 2);
            const int r2 = r1 + 8;
            const float* a4 = acc[mt][nt];
            *(float2*)&job.C[(long long)r1 * ldc + col] = make_float2(a4[0] + bv0, a4[1] + bv1);
            *(float2*)&job.C[(long long)r2 * ldc + col] = make_float2(a4[2] + bv0, a4[3] + bv1);
        }
    }
}

// ---------------- weight transpose + fp16 split (once per call) -----------------
__global__ void wconv_k(const float* __restrict__ Win, const float* __restrict__ Wout,
                        const float* __restrict__ Wr, const float* __restrict__ Wz,
                        const float* __restrict__ Wt,
                        __half* __restrict__ wth, __half* __restrict__ wtl) {
    __shared__ float tile[32][33];
    const int slot = blockIdx.z;
    const int f0 = blockIdx.x * 32, d0 = blockIdx.y * 32;
    const float* base;
    if (slot < 6)       base = Win  + (long long)slot * DDLL;
    else if (slot < 12) base = Wout + (long long)(slot - 6) * DDLL;
    else {
        int gq = (slot - 12) / 3, q = (slot - 12) % 3;
        base = (gq == 0 ? Wr : (gq == 1 ? Wz : Wt)) + (long long)q * DDLL;
    }
    for (int i = threadIdx.y; i < 32; i += 8)
        tile[i][threadIdx.x] = base[(long long)(d0 + i) * 1280 + f0 + threadIdx.x];
    __syncthreads();
    __half* oh = wth + (long long)slot * DDLL;
    __half* ol = wtl + (long long)slot * DDLL;
    for (int i = threadIdx.y; i < 32; i += 8) {
        float v = tile[threadIdx.x][i];
        __half h, l; split2h(v, h, l);
        oh[(long long)(f0 + i) * 1280 + d0 + threadIdx.x] = h;
        ol[(long long)(f0 + i) * 1280 + d0 + threadIdx.x] = l;
    }
}

// ---------------- elementwise kernels (node-major) ------------------------------
__global__ void copy_x_k(const float* __restrict__ x, float* __restrict__ gx,
                         __half* __restrict__ gf) {
    for (long long j = blockIdx.x * blockDim.x + threadIdx.x; j < TOT;
         j += (long long)gridDim.x * blockDim.x) {
        int n = (int)(j / BD);
        long long rem = j - (long long)n * BD;
        int b = (int)(rem / D_), d = (int)(rem % D_);
        float v = x[((long long)b * N_ + n) * D_ + d];
        gx[j] = v;
        gf[j] = __float2half(v);
    }
}

__global__ void sig_rgx_k(const float* __restrict__ prer, const float* __restrict__ gx,
                          __half* __restrict__ rf) {
    for (int i = blockIdx.x * blockDim.x + threadIdx.x; i < TOT; i += gridDim.x * blockDim.x) {
        float r = 1.f / (1.f + expf(-prer[i]));
        rf[i] = __float2half(r * gx[i]);
    }
}

__global__ void update_k(const float* __restrict__ prez, const float* __restrict__ pret,
                         const float* __restrict__ pretD, const float* __restrict__ b_t,
                         float* __restrict__ gx, __half* __restrict__ gf) {
    const long long lim = 4LL * BD;
    for (long long i = blockIdx.x * blockDim.x + threadIdx.x; i < TOT;
         i += (long long)gridDim.x * blockDim.x) {
        float pt = (i < lim) ? pret[i] : b_t[(int)(i % D_)];
        float z = 1.f / (1.f + expf(-prez[i]));
        float h = tanhf(pt + pretD[i]);
        float gv = gx[i];
        float ng = gv + z * (h - gv);
        gx[i] = ng;
        gf[i] = __float2half(ng);
    }
}

__global__ void transpose_k(const float* __restrict__ gx, float* __restrict__ out) {
    for (long long idx = blockIdx.x * blockDim.x + threadIdx.x; idx < TOT;
         idx += (long long)gridDim.x * blockDim.x) {
        int b = (int)(idx / ((long long)N_ * D_));
        long long r = idx - (long long)b * N_ * D_;
        int d = (int)(r / N_), n = (int)(r % N_);
        out[idx] = gx[((long long)n * B_ + b) * D_ + d];
    }
}

// ---------------- host orchestration ------------------------------------------
extern "C" void kernel_launch(void* const* d_in, const int* in_sizes, int n_in,
                              void* d_out, int out_size) {
    const float* x     = (const float*)d_in[0];
    const float* W_in  = (const float*)d_in[2];
    const float* b_in  = (const float*)d_in[3];
    const float* W_out = (const float*)d_in[4];
    const float* b_out = (const float*)d_in[5];
    const float* W_r   = (const float*)d_in[6];
    const float* b_r   = (const float*)d_in[7];
    const float* W_z   = (const float*)d_in[8];
    const float* b_z   = (const float*)d_in[9];
    const float* W_t   = (const float*)d_in[10];
    const float* b_t   = (const float*)d_in[11];
    float* out = (float*)d_out;

    float *gx, *prer, *prez, *pret, *pretD;
    __half *gxf, *ainf, *aoutf, *rgxf, *wth, *wtl;
    cudaGetSymbolAddress((void**)&gx,    g_gx);
    cudaGetSymbolAddress((void**)&prer,  g_prer);
    cudaGetSymbolAddress((void**)&prez,  g_prez);
    cudaGetSymbolAddress((void**)&pret,  g_pret);
    cudaGetSymbolAddress((void**)&pretD, g_pretD);
    cudaGetSymbolAddress((void**)&gxf,   g_gxf);
    cudaGetSymbolAddress((void**)&ainf,  g_ainf);
    cudaGetSymbolAddress((void**)&aoutf, g_aoutf);
    cudaGetSymbolAddress((void**)&rgxf,  g_rgxf);
    cudaGetSymbolAddress((void**)&wth,   g_wth);
    cudaGetSymbolAddress((void**)&wtl,   g_wtl);

    cudaFuncSetAttribute(mma_gemm,   cudaFuncAttributeMaxDynamicSharedMemorySize, SMEM_TOTAL);
    cudaFuncSetAttribute(mma_gemmA,  cudaFuncAttributeMaxDynamicSharedMemorySize, SMEM_A_TOTAL);
    cudaFuncSetAttribute(mma_gemm1p, cudaFuncAttributeMaxDynamicSharedMemorySize, SMEM_1P_TOTAL);

    static cudaStream_t s1 = nullptr;
    static cudaEvent_t evFork = nullptr, evJoin = nullptr;
    if (!s1) {
        cudaStreamCreateWithFlags(&s1, cudaStreamNonBlocking);
        cudaEventCreateWithFlags(&evFork, cudaEventDisableTiming);
        cudaEventCreateWithFlags(&evJoin, cudaEventDisableTiming);
    }

    auto wslot = [&](int s) { return (long long)s * DDLL; };

    // ---- Phase A (mode 0): edge propagation, node-major, 2-pass ----
    GBatch bA = {};
    {
        auto seg_in = [&](int src, int et) {
            GSeg s{};
            s.A = gxf + (long long)src * BD; s.lda = D_;
            s.Bh = wth + wslot(et); s.Bl = wtl + wslot(et);
            s.bias = b_in + (long long)et * D_;
            return s;
        };
        auto seg_out = [&](int tgt, int et) {
            GSeg s{};
            s.A = gxf + (long long)tgt * BD; s.lda = D_;
            s.Bh = wth + wslot(6 + et); s.Bl = wtl + wslot(6 + et);
            s.bias = b_out + (long long)et * D_;
            return s;
        };
        auto setC = [&](GJob& j, __half* cf, int node) {
            j.Ch = cf + (long long)node * BD;
            j.ldc = D_; j.mode = 0; j.M = B_;
        };
        bA.job[0].seg[0] = seg_in(0, 2); bA.job[0].seg[1] = seg_in(1, 4); bA.job[0].seg[2] = seg_in(2, 5);
        bA.job[0].nseg = 3; setC(bA.job[0], ainf, 3);
        bA.job[1].seg[0] = seg_out(1, 0); bA.job[1].seg[1] = seg_out(2, 1); bA.job[1].seg[2] = seg_out(3, 2);
        bA.job[1].nseg = 3; setC(bA.job[1], aoutf, 0);
        bA.job[2].seg[0] = seg_in(0, 1); bA.job[2].seg[1] = seg_in(1, 3);
        bA.job[2].nseg = 2; setC(bA.job[2], ainf, 2);
        bA.job[3].seg[0] = seg_out(2, 3); bA.job[3].seg[1] = seg_out(3, 4);
        bA.job[3].nseg = 2; setC(bA.job[3], aoutf, 1);
        bA.job[4].seg[0] = seg_in(0, 0); bA.job[4].nseg = 1; setC(bA.job[4], ainf, 1);
        bA.job[5].seg[0] = seg_out(3, 5); bA.job[5].nseg = 1; setC(bA.job[5], aoutf, 2);
    }

    auto mkseg = [&](const __half* A, int node, int gslot, const float* bias, bool lo) {
        GSeg s{};
        s.A = A + (long long)node * BD; s.lda = D_;
        s.Bh = wth + wslot(gslot); s.Bl = lo ? (wtl + wslot(gslot)) : nullptr;
        s.bias = bias;
        return s;
    };

    // ---- R launch (1-pass kernel): prer by node group ----
    GBatch bR = {};
    bR.job[0].seg[0] = mkseg(ainf, 1, 12, b_r, false);
    bR.job[0].seg[1] = mkseg(aoutf, 1, 13, 0, false);
    bR.job[0].seg[2] = mkseg(gxf, 1, 14, 0, false);
    bR.job[0].nseg = 3; bR.job[0].C = prer + BD; bR.job[0].ldc = D_; bR.job[0].mode = 1; bR.job[0].M = 2 * B_;
    bR.job[1].seg[0] = mkseg(gxf, 4, 14, b_r, false);
    bR.job[1].nseg = 1; bR.job[1].C = prer + 4 * BD; bR.job[1].ldc = D_; bR.job[1].mode = 1; bR.job[1].M = 2 * B_;
    bR.job[2].seg[0] = mkseg(aoutf, 0, 13, b_r, false);
    bR.job[2].seg[1] = mkseg(gxf, 0, 14, 0, false);
    bR.job[2].nseg = 2; bR.job[2].C = prer; bR.job[2].ldc = D_; bR.job[2].mode = 1; bR.job[2].M = B_;
    bR.job[3].seg[0] = mkseg(ainf, 3, 12, b_r, false);
    bR.job[3].seg[1] = mkseg(gxf, 3, 14, 0, false);
    bR.job[3].nseg = 2; bR.job[3].C = prer + 3 * BD; bR.job[3].ldc = D_; bR.job[3].mode = 1; bR.job[3].M = B_;

    // ---- Z launch (1-pass kernel): prez by node group ----
    GBatch bZ = {};
    bZ.job[0].seg[0] = mkseg(ainf, 1, 15, b_z, false);
    bZ.job[0].seg[1] = mkseg(aoutf, 1, 16, 0, false);
    bZ.job[0].seg[2] = mkseg(gxf, 1, 17, 0, false);
    bZ.job[0].nseg = 3; bZ.job[0].C = prez + BD; bZ.job[0].ldc = D_; bZ.job[0].mode = 1; bZ.job[0].M = 2 * B_;
    bZ.job[1].seg[0] = mkseg(gxf, 4, 17, b_z, false);
    bZ.job[1].nseg = 1; bZ.job[1].C = prez + 4 * BD; bZ.job[1].ldc = D_; bZ.job[1].mode = 1; bZ.job[1].M = 2 * B_;
    bZ.job[2].seg[0] = mkseg(aoutf, 0, 16, b_z, false);
    bZ.job[2].seg[1] = mkseg(gxf, 0, 17, 0, false);
    bZ.job[2].nseg = 2; bZ.job[2].C = prez; bZ.job[2].ldc = D_; bZ.job[2].mode = 1; bZ.job[2].M = B_;
    bZ.job[3].seg[0] = mkseg(ainf, 3, 15, b_z, false);
    bZ.job[3].seg[1] = mkseg(gxf, 3, 17, 0, false);
    bZ.job[3].nseg = 2; bZ.job[3].C = prez + 3 * BD; bZ.job[3].ldc = D_; bZ.job[3].mode = 1; bZ.job[3].M = B_;

    // ---- T launch (small kernel, 2-pass): pret partial ----
    GBatch bT = {};
    bT.job[0].seg[0] = mkseg(ainf, 1, 18, b_t, true);
    bT.job[0].seg[1] = mkseg(aoutf, 1, 19, 0, true);
    bT.job[0].nseg = 2; bT.job[0].C = pret + BD; bT.job[0].ldc = D_; bT.job[0].mode = 1; bT.job[0].M = 2 * B_;
    bT.job[1].seg[0] = mkseg(aoutf, 0, 19, b_t, true);
    bT.job[1].nseg = 1; bT.job[1].C = pret; bT.job[1].ldc = D_; bT.job[1].mode = 1; bT.job[1].M = B_;
    bT.job[2].seg[0] = mkseg(ainf, 3, 18, b_t, true);
    bT.job[2].nseg = 1; bT.job[2].C = pret + 3 * BD; bT.job[2].ldc = D_; bT.job[2].mode = 1; bT.job[2].M = B_;

    // ---- D launch (128x128, 2-pass): pretD = (r*gx) @ Wt2, all nodes ----
    GBatch bD = {};
    {
        GSeg s{};
        s.A = rgxf; s.lda = D_;
        s.Bh = wth + wslot(20); s.Bl = wtl + wslot(20); s.bias = 0;
        bD.job[0].seg[0] = s; bD.job[0].nseg = 1;
        bD.job[0].C = pretD; bD.job[0].ldc = D_; bD.job[0].mode = 1; bD.job[0].M = N_ * B_;
    }

    // ---- run ----
    wconv_k<<<dim3(40, 40, 21), dim3(32, 8)>>>(W_in, W_out, W_r, W_z, W_t, wth, wtl);
    copy_x_k<<<2048, 256>>>(x, gx, gxf);

    for (int step = 0; step < STEPS_; step++) {
        mma_gemmA<<<dim3(20, 8, 6),  256, SMEM_A_TOTAL>>>(bA);   // edges (2-pass)
        mma_gemm1p<<<dim3(10, 16, 4), 256, SMEM_1P_TOTAL>>>(bR); // prer (1-pass, wide tiles)
        cudaEventRecord(evFork, 0);
        cudaStreamWaitEvent(s1, evFork, 0);
        sig_rgx_k<<<2048, 256, 0, s1>>>(prer, gx, rgxf);                 // side stream
        mma_gemm<<<dim3(10, 48, 1), 256, SMEM_TOTAL, s1>>>(bD);          // pretD (2-pass)
        cudaEventRecord(evJoin, s1);
        mma_gemm1p<<<dim3(10, 16, 4), 256, SMEM_1P_TOTAL>>>(bZ); // prez (1-pass, wide tiles)
        mma_gemmA<<<dim3(20, 16, 3), 256, SMEM_A_TOTAL>>>(bT);   // pret partial (2-pass)
        cudaStreamWaitEvent(0, evJoin, 0);
        update_k<<<2048, 256>>>(prez, pret, pretD, b_t, gx, gxf);
    }
    transpose_k<<<2048, 256>>>(gx, out);
}